// round 8
// baseline (speedup 1.0000x reference)
#include <cuda_runtime.h>
#include <cstddef>

#define N_USERS 200000
#define N_MOVIES 80000
#define NN 280000
#define HDIM 64
#define F_MOVIE 20
#define NE 1250000
#define NEL 500000
#define NB2 274           // ceil(NN / 1024)

typedef unsigned long long u64;

// Scratch (static device globals: allowed; runtime allocation is not).
__device__ __align__(16) float g_X[(size_t)NN * HDIM];
__device__ __align__(16) float g_Y[(size_t)NN * HDIM];
__device__ __align__(16) float g_Z[(size_t)NN * HDIM];
__device__ __align__(16) float g_M[(size_t)NN * HDIM];
__device__ int g_DEGI[NN];
__device__ int g_OFF[NN + 1];
__device__ int g_CUR[NN];
__device__ int g_CSR[NE];
__device__ int g_PREF[NB2];
__device__ int g_FLAG[NB2];

// ---- packed f32x2 helpers (Blackwell FFMA2 path, PTX-only) -----------------
__device__ __forceinline__ u64 pack2(float lo, float hi) {
    u64 r; asm("mov.b64 %0, {%1, %2};" : "=l"(r) : "f"(lo), "f"(hi)); return r;
}
__device__ __forceinline__ u64 bcast2(float x) {
    u64 r; asm("mov.b64 %0, {%1, %1};" : "=l"(r) : "f"(x)); return r;
}
__device__ __forceinline__ u64 ffma2(u64 a, u64 b, u64 c) {
    u64 d; asm("fma.rn.f32x2 %0, %1, %2, %3;" : "=l"(d) : "l"(a), "l"(b), "l"(c));
    return d;
}
__device__ __forceinline__ float2 unpack2(u64 v) {
    float2 f; asm("mov.b64 {%0, %1}, %2;" : "=f"(f.x), "=f"(f.y) : "l"(v)); return f;
}

// ---------------------------------------------------------------------------
// 1) hist: degi[dst]++ per edge
// ---------------------------------------------------------------------------
__global__ void hist_kernel(const int* __restrict__ ei, int* __restrict__ degi) {
    int e = blockIdx.x * blockDim.x + threadIdx.x;
    if (e < NE) atomicAdd(&degi[ei[NE + e]], 1);
}

// ---------------------------------------------------------------------------
// 2) single-pass chained exclusive scan of degi -> off, cur.
// 274 blocks, all co-resident -> chained spin is deadlock-free.
// ---------------------------------------------------------------------------
__global__ void scan_chain_kernel(const int* __restrict__ degi,
                                  int* __restrict__ off, int* __restrict__ cur,
                                  volatile int* __restrict__ pref,
                                  volatile int* __restrict__ flag) {
    __shared__ int ss[256];
    __shared__ int s_prefix;
    int b = blockIdx.x, t = threadIdx.x;
    int i0 = b * 1024 + t * 4;
    int v[4];
    int tot = 0;
#pragma unroll
    for (int j = 0; j < 4; j++) {
        int i = i0 + j;
        v[j] = (i < NN) ? degi[i] : 0;
        tot += v[j];
    }
    ss[t] = tot;
    __syncthreads();
#pragma unroll
    for (int o = 1; o < 256; o <<= 1) {
        int x = (t >= o) ? ss[t - o] : 0;
        __syncthreads();
        ss[t] += x;
        __syncthreads();
    }
    // chained prefix
    if (t == 0) {
        int p = 0;
        if (b > 0) {
            while (flag[b - 1] == 0) { }
            __threadfence();
            p = pref[b - 1];
        }
        pref[b] = p + ss[255];
        __threadfence();
        flag[b] = 1;
        s_prefix = p;
        if (b == 0) off[NN] = NE;
    }
    __syncthreads();
    int run = s_prefix + ((t == 0) ? 0 : ss[t - 1]);
#pragma unroll
    for (int j = 0; j < 4; j++) {
        int i = i0 + j;
        if (i < NN) { off[i] = run; cur[i] = run; }
        run += v[j];
    }
}

// ---------------------------------------------------------------------------
// 3) fused: CSR fill (edge-parallel)  +  X init (row-parallel)
// ---------------------------------------------------------------------------
__global__ void fill_init_kernel(const int* __restrict__ ei,
                                 int* __restrict__ cur, int* __restrict__ csr,
                                 const float* __restrict__ movie_x,
                                 const float* __restrict__ user_emb,
                                 const float* __restrict__ movie_emb,
                                 const float* __restrict__ lin_W,
                                 const float* __restrict__ lin_b,
                                 float* __restrict__ X) {
    int gid = blockIdx.x * blockDim.x + threadIdx.x;
    if (gid < NE) {
        int src = ei[gid];
        int dst = ei[NE + gid];
        int p = atomicAdd(&cur[dst], 1);
        csr[p] = src;
    }
    // init_X part: 4 rows per block of 256
    __shared__ float sx[4][F_MOVIE];
    int lr  = threadIdx.x >> 6;
    int h   = threadIdx.x & 63;
    int row = blockIdx.x * 4 + lr;
    int mrow = row - N_USERS;
    if (row < NN && mrow >= 0 && h < F_MOVIE)
        sx[lr][h] = movie_x[mrow * F_MOVIE + h];
    __syncthreads();
    if (row >= NN) return;
    if (mrow < 0) {
        X[(size_t)row * HDIM + h] = user_emb[(size_t)row * HDIM + h];
    } else {
        float acc = lin_b[h] + movie_emb[(size_t)mrow * HDIM + h];
#pragma unroll
        for (int f = 0; f < F_MOVIE; f++)
            acc += sx[lr][f] * lin_W[h * F_MOVIE + f];
        X[(size_t)row * HDIM + h] = acc;
    }
}

// ---------------------------------------------------------------------------
// 4) MEAN[row] = mean over neighbors — warp per row, float2 lanes, MLP=4.
// ---------------------------------------------------------------------------
__global__ void __launch_bounds__(256)
gather_kernel(const float* __restrict__ Xin,
              const int* __restrict__ off, const int* __restrict__ csr,
              float* __restrict__ MEAN) {
    int row  = (blockIdx.x * blockDim.x + threadIdx.x) >> 5;
    int lane = threadIdx.x & 31;
    if (row >= NN) return;
    int s0 = __ldg(&off[row]);
    int s1 = __ldg(&off[row + 1]);
    float2 acc = make_float2(0.f, 0.f);
    for (int e = s0; e < s1; e += 4) {
        int i0 = (e     < s1) ? __ldg(&csr[e])     : -1;
        int i1 = (e + 1 < s1) ? __ldg(&csr[e + 1]) : -1;
        int i2 = (e + 2 < s1) ? __ldg(&csr[e + 2]) : -1;
        int i3 = (e + 3 < s1) ? __ldg(&csr[e + 3]) : -1;
        float2 v0 = (i0 >= 0) ? *(const float2*)&Xin[(size_t)i0 * HDIM + lane * 2]
                              : make_float2(0.f, 0.f);
        float2 v1 = (i1 >= 0) ? *(const float2*)&Xin[(size_t)i1 * HDIM + lane * 2]
                              : make_float2(0.f, 0.f);
        float2 v2 = (i2 >= 0) ? *(const float2*)&Xin[(size_t)i2 * HDIM + lane * 2]
                              : make_float2(0.f, 0.f);
        float2 v3 = (i3 >= 0) ? *(const float2*)&Xin[(size_t)i3 * HDIM + lane * 2]
                              : make_float2(0.f, 0.f);
        acc.x += (v0.x + v1.x) + (v2.x + v3.x);
        acc.y += (v0.y + v1.y) + (v2.y + v3.y);
    }
    float inv = 1.f / fmaxf((float)(s1 - s0), 1.f);
    acc.x *= inv; acc.y *= inv;
    *(float2*)&MEAN[(size_t)row * HDIM + lane * 2] = acc;
}

// ---------------------------------------------------------------------------
// Y = act( MEAN @ Wl.T + bl + Xin @ Wr.T )
// 256 threads, 256-row tile, thread tile 8 rows x 8 cols.
// STRIDED row mapping (row = g + i*32): input LDS are 8-thread broadcast AND
// bank-conflict-free (stride 68 floats -> 4 distinct bank groups), so the
// kernel is FFMA2-issue-bound, not smem-crossbar-bound.
// smem: sW [64][68] + sIn [256][68] = 87 KB -> 2 blocks/SM.
// ---------------------------------------------------------------------------
#define WPAD 68
#define RPB  256

__device__ __forceinline__ void accum_phase88(const float* __restrict__ sW,
                                              const float* __restrict__ sIn,
                                              int g, int h0, u64 acc[8][4]) {
#pragma unroll
    for (int k = 0; k < 64; k += 4) {
        float4 v[8];
#pragma unroll
        for (int i = 0; i < 8; i++)
            v[i] = *(const float4*)&sIn[(g + i * 32) * WPAD + k];
#pragma unroll
        for (int kk = 0; kk < 4; kk++) {
            ulonglong2 wa = *(const ulonglong2*)&sW[(k + kk) * WPAD + h0];
            ulonglong2 wb = *(const ulonglong2*)&sW[(k + kk) * WPAD + h0 + 4];
#pragma unroll
            for (int i = 0; i < 8; i++) {
                float s = (kk == 0) ? v[i].x : (kk == 1) ? v[i].y
                        : (kk == 2) ? v[i].z : v[i].w;
                u64 t = bcast2(s);
                acc[i][0] = ffma2(t, wa.x, acc[i][0]);
                acc[i][1] = ffma2(t, wa.y, acc[i][1]);
                acc[i][2] = ffma2(t, wb.x, acc[i][2]);
                acc[i][3] = ffma2(t, wb.y, acc[i][3]);
            }
        }
    }
}

template <bool RELU>
__global__ void __launch_bounds__(256, 2)
combine_kernel(const float* __restrict__ Xin, const float* __restrict__ MEAN,
               const float* __restrict__ Wl, const float* __restrict__ bl,
               const float* __restrict__ Wr, float* __restrict__ Y) {
    extern __shared__ float smem[];
    float* sW  = smem;               // [64][WPAD]
    float* sIn = smem + 64 * WPAD;   // [256][WPAD]
    __shared__ float sb[64];

    int tid  = threadIdx.x;
    int base = blockIdx.x * RPB;
    int g    = tid >> 3;             // 0..31 row group
    int h0   = (tid & 7) * 8;        // 8-wide output columns

    // phase-1: Wl^T + MEAN tile
    for (int i = tid; i < 64 * 64; i += 256) {
        int h = i >> 6, k = i & 63;
        sW[k * WPAD + h] = Wl[i];
    }
    if (tid < 64) sb[tid] = bl[tid];
    for (int i = tid; i < RPB * 16; i += 256) {
        int r = i >> 4, k4 = (i & 15) * 4;
        int row = base + r;
        float4 v = make_float4(0.f, 0.f, 0.f, 0.f);
        if (row < NN) v = *(const float4*)&MEAN[(size_t)row * HDIM + k4];
        *(float4*)&sIn[r * WPAD + k4] = v;
    }
    __syncthreads();

    u64 acc[8][4];
    {
        u64 b0 = pack2(sb[h0],     sb[h0 + 1]);
        u64 b1 = pack2(sb[h0 + 2], sb[h0 + 3]);
        u64 b2 = pack2(sb[h0 + 4], sb[h0 + 5]);
        u64 b3 = pack2(sb[h0 + 6], sb[h0 + 7]);
#pragma unroll
        for (int i = 0; i < 8; i++) {
            acc[i][0] = b0; acc[i][1] = b1; acc[i][2] = b2; acc[i][3] = b3;
        }
    }

    accum_phase88(sW, sIn, g, h0, acc);     // mean @ Wl^T
    __syncthreads();

    // phase-2: Wr^T + x tile
    for (int i = tid; i < 64 * 64; i += 256) {
        int h = i >> 6, k = i & 63;
        sW[k * WPAD + h] = Wr[i];
    }
    for (int i = tid; i < RPB * 16; i += 256) {
        int r = i >> 4, k4 = (i & 15) * 4;
        int row = base + r;
        float4 v = make_float4(0.f, 0.f, 0.f, 0.f);
        if (row < NN) v = *(const float4*)&Xin[(size_t)row * HDIM + k4];
        *(float4*)&sIn[r * WPAD + k4] = v;
    }
    __syncthreads();

    accum_phase88(sW, sIn, g, h0, acc);     // + x @ Wr^T

#pragma unroll
    for (int i = 0; i < 8; i++) {
        int row = base + g + i * 32;
        if (row < NN) {
            float2 p0 = unpack2(acc[i][0]);
            float2 p1 = unpack2(acc[i][1]);
            float2 p2 = unpack2(acc[i][2]);
            float2 p3 = unpack2(acc[i][3]);
            float4 oA = make_float4(p0.x, p0.y, p1.x, p1.y);
            float4 oB = make_float4(p2.x, p2.y, p3.x, p3.y);
            if (RELU) {
                oA.x = fmaxf(oA.x, 0.f); oA.y = fmaxf(oA.y, 0.f);
                oA.z = fmaxf(oA.z, 0.f); oA.w = fmaxf(oA.w, 0.f);
                oB.x = fmaxf(oB.x, 0.f); oB.y = fmaxf(oB.y, 0.f);
                oB.z = fmaxf(oB.z, 0.f); oB.w = fmaxf(oB.w, 0.f);
            }
            *(float4*)&Y[(size_t)row * HDIM + h0]     = oA;
            *(float4*)&Y[(size_t)row * HDIM + h0 + 4] = oB;
        }
    }
}

// ---------------------------------------------------------------------------
// out[e] = dot(Z[u[e]], Z[N_USERS + m[e]]) — 16 lanes per label edge, float4
// ---------------------------------------------------------------------------
__global__ void dot_kernel(const int* __restrict__ eli,
                           const float* __restrict__ Z,
                           float* __restrict__ out) {
    int gw = (blockIdx.x * blockDim.x + threadIdx.x) >> 4;
    int l  = threadIdx.x & 15;
    if (gw >= NEL) return;
    int u = __ldg(&eli[gw]);
    int m = __ldg(&eli[NEL + gw]);
    float4 a = *(const float4*)&Z[(size_t)u * HDIM + l * 4];
    float4 b = *(const float4*)&Z[(size_t)(N_USERS + m) * HDIM + l * 4];
    float s = a.x * b.x + a.y * b.y + a.z * b.z + a.w * b.w;
#pragma unroll
    for (int o = 8; o; o >>= 1) s += __shfl_xor_sync(0xffffffffu, s, o);
    if (l == 0) out[gw] = s;
}

// ---------------------------------------------------------------------------
extern "C" void kernel_launch(void* const* d_in, const int* in_sizes, int n_in,
                              void* d_out, int out_size) {
    const float* movie_x   = (const float*)d_in[0];
    const float* user_emb  = (const float*)d_in[1];
    const float* movie_emb = (const float*)d_in[2];
    const float* lin_W     = (const float*)d_in[3];
    const float* lin_b     = (const float*)d_in[4];
    const float* W1l       = (const float*)d_in[5];
    const float* b1        = (const float*)d_in[6];
    const float* W1r       = (const float*)d_in[7];
    const float* W2l       = (const float*)d_in[8];
    const float* b2        = (const float*)d_in[9];
    const float* W2r       = (const float*)d_in[10];
    const int*   ei        = (const int*)d_in[11];
    const int*   eli       = (const int*)d_in[12];
    float* out = (float*)d_out;

    float *dX, *dY, *dZ, *dM;
    int *dDEGI, *dOFF, *dCUR, *dCSR, *dPREF, *dFLAG;
    cudaGetSymbolAddress((void**)&dX,    g_X);
    cudaGetSymbolAddress((void**)&dY,    g_Y);
    cudaGetSymbolAddress((void**)&dZ,    g_Z);
    cudaGetSymbolAddress((void**)&dM,    g_M);
    cudaGetSymbolAddress((void**)&dDEGI, g_DEGI);
    cudaGetSymbolAddress((void**)&dOFF,  g_OFF);
    cudaGetSymbolAddress((void**)&dCUR,  g_CUR);
    cudaGetSymbolAddress((void**)&dCSR,  g_CSR);
    cudaGetSymbolAddress((void**)&dPREF, g_PREF);
    cudaGetSymbolAddress((void**)&dFLAG, g_FLAG);

    const size_t smemC = (size_t)((64 + RPB) * WPAD) * sizeof(float); // 87 KB
    cudaFuncSetAttribute(combine_kernel<true>,
                         cudaFuncAttributeMaxDynamicSharedMemorySize, (int)smemC);
    cudaFuncSetAttribute(combine_kernel<false>,
                         cudaFuncAttributeMaxDynamicSharedMemorySize, (int)smemC);

    const int gridC = (NN + RPB - 1) / RPB;   // 1094
    const int gridG = (NN * 32 + 255) / 256;  // warp per row
    const int gridF = (NN + 3) / 4;           // fill+init (covers NE too)

    // ---- CSR build + node features ----
    cudaMemsetAsync(dDEGI, 0, NN * sizeof(int));
    cudaMemsetAsync(dFLAG, 0, NB2 * sizeof(int));
    hist_kernel<<<(NE + 255) / 256, 256>>>(ei, dDEGI);                   // #1
    scan_chain_kernel<<<NB2, 256>>>(dDEGI, dOFF, dCUR, dPREF, dFLAG);    // #2
    fill_init_kernel<<<gridF, 256>>>(ei, dCUR, dCSR, movie_x, user_emb,
                                     movie_emb, lin_W, lin_b, dX);       // #3

    // ---- layer 1 ----
    gather_kernel<<<gridG, 256>>>(dX, dOFF, dCSR, dM);                   // #4 (profiled)
    combine_kernel<true><<<gridC, 256, smemC>>>(dX, dM, W1l, b1, W1r, dY); // #5

    // ---- layer 2 ----
    gather_kernel<<<gridG, 256>>>(dY, dOFF, dCSR, dM);                   // #6
    combine_kernel<false><<<gridC, 256, smemC>>>(dY, dM, W2l, b2, W2r, dZ); // #7

    // ---- decode ----
    dot_kernel<<<(NEL * 16) / 256, 256>>>(eli, dZ, out);                 // #8
}

// round 9
// speedup vs baseline: 1.0652x; 1.0652x over previous
#include <cuda_runtime.h>
#include <cstddef>

#define N_USERS 200000
#define N_MOVIES 80000
#define NN 280000
#define HDIM 64
#define F_MOVIE 20
#define NE 1250000
#define NEL 500000
#define NB2 274           // ceil(NN / 1024)

typedef unsigned long long u64;

// Scratch (static device globals: allowed; runtime allocation is not).
__device__ __align__(16) float g_X[(size_t)NN * HDIM];
__device__ __align__(16) float g_Y[(size_t)NN * HDIM];
__device__ __align__(16) float g_Z[(size_t)NN * HDIM];
__device__ __align__(16) float g_M[(size_t)NN * HDIM];
__device__ int g_DEGI[NN];
__device__ int g_OFF[NN + 1];
__device__ int g_CUR[NN];
__device__ int g_CSR[NE];      // holds src*HDIM (premultiplied)
__device__ int g_PREF[NB2];
__device__ int g_FLAG[NB2];

// ---- packed f32x2 helpers ---------------------------------------------------
__device__ __forceinline__ u64 pack2(float lo, float hi) {
    u64 r; asm("mov.b64 %0, {%1, %2};" : "=l"(r) : "f"(lo), "f"(hi)); return r;
}
__device__ __forceinline__ u64 ffma2(u64 a, u64 b, u64 c) {
    u64 d; asm("fma.rn.f32x2 %0, %1, %2, %3;" : "=l"(d) : "l"(a), "l"(b), "l"(c));
    return d;
}
__device__ __forceinline__ float2 unpack2(u64 v) {
    float2 f; asm("mov.b64 {%0, %1}, %2;" : "=f"(f.x), "=f"(f.y) : "l"(v)); return f;
}

// ---------------------------------------------------------------------------
// 1) fused: X init (row-parallel) + degree histogram (edge-parallel) + flag zero
// ---------------------------------------------------------------------------
__global__ void init_hist_kernel(const int* __restrict__ ei,
                                 int* __restrict__ degi, int* __restrict__ flag,
                                 const float* __restrict__ movie_x,
                                 const float* __restrict__ user_emb,
                                 const float* __restrict__ movie_emb,
                                 const float* __restrict__ lin_W,
                                 const float* __restrict__ lin_b,
                                 float* __restrict__ X) {
    int gid = blockIdx.x * blockDim.x + threadIdx.x;
    if (gid < NE) atomicAdd(&degi[ei[NE + gid]], 1);
    if (gid < NB2) flag[gid] = 0;

    __shared__ float sx[4][F_MOVIE];
    int lr  = threadIdx.x >> 6;
    int h   = threadIdx.x & 63;
    int row = blockIdx.x * 4 + lr;
    int mrow = row - N_USERS;
    if (row < NN && mrow >= 0 && h < F_MOVIE)
        sx[lr][h] = movie_x[mrow * F_MOVIE + h];
    __syncthreads();
    if (row >= NN) return;
    if (mrow < 0) {
        X[(size_t)row * HDIM + h] = user_emb[(size_t)row * HDIM + h];
    } else {
        float acc = lin_b[h] + movie_emb[(size_t)mrow * HDIM + h];
#pragma unroll
        for (int f = 0; f < F_MOVIE; f++)
            acc += sx[lr][f] * lin_W[h * F_MOVIE + f];
        X[(size_t)row * HDIM + h] = acc;
    }
}

// ---------------------------------------------------------------------------
// 2) single-pass chained exclusive scan of degi -> off, cur (274 co-resident blocks)
// ---------------------------------------------------------------------------
__global__ void scan_chain_kernel(const int* __restrict__ degi,
                                  int* __restrict__ off, int* __restrict__ cur,
                                  volatile int* __restrict__ pref,
                                  volatile int* __restrict__ flag) {
    __shared__ int ss[256];
    __shared__ int s_prefix;
    int b = blockIdx.x, t = threadIdx.x;
    int i0 = b * 1024 + t * 4;
    int v[4];
    int tot = 0;
#pragma unroll
    for (int j = 0; j < 4; j++) {
        int i = i0 + j;
        v[j] = (i < NN) ? degi[i] : 0;
        tot += v[j];
    }
    ss[t] = tot;
    __syncthreads();
#pragma unroll
    for (int o = 1; o < 256; o <<= 1) {
        int x = (t >= o) ? ss[t - o] : 0;
        __syncthreads();
        ss[t] += x;
        __syncthreads();
    }
    if (t == 0) {
        int p = 0;
        if (b > 0) {
            while (flag[b - 1] == 0) { }
            __threadfence();
            p = pref[b - 1];
        }
        pref[b] = p + ss[255];
        __threadfence();
        flag[b] = 1;
        s_prefix = p;
        if (b == 0) off[NN] = NE;
    }
    __syncthreads();
    int run = s_prefix + ((t == 0) ? 0 : ss[t - 1]);
#pragma unroll
    for (int j = 0; j < 4; j++) {
        int i = i0 + j;
        if (i < NN) { off[i] = run; cur[i] = run; }
        run += v[j];
    }
}

// ---------------------------------------------------------------------------
// 3) CSR fill — stores src*HDIM so gather needs no multiply
// ---------------------------------------------------------------------------
__global__ void fill_kernel(const int* __restrict__ ei,
                            int* __restrict__ cur, int* __restrict__ csr) {
    int e = blockIdx.x * blockDim.x + threadIdx.x;
    if (e >= NE) return;
    int src = ei[e];
    int dst = ei[NE + e];
    int p = atomicAdd(&cur[dst], 1);
    csr[p] = src * HDIM;
}

// ---------------------------------------------------------------------------
// 4) MEAN[row] = mean over neighbors — warp per row, float2 lanes, MLP=4,
//    premultiplied csr indices (no IMAD.WIDE in the loop).
// ---------------------------------------------------------------------------
__global__ void __launch_bounds__(256)
gather_kernel(const float* __restrict__ Xin,
              const int* __restrict__ off, const int* __restrict__ csr,
              float* __restrict__ MEAN) {
    int row  = (blockIdx.x * blockDim.x + threadIdx.x) >> 5;
    int lane = threadIdx.x & 31;
    if (row >= NN) return;
    int s0 = __ldg(&off[row]);
    int s1 = __ldg(&off[row + 1]);
    const float* Xl = Xin + lane * 2;
    float2 acc = make_float2(0.f, 0.f);
    for (int e = s0; e < s1; e += 4) {
        int i0 = (e     < s1) ? __ldg(&csr[e])     : -1;
        int i1 = (e + 1 < s1) ? __ldg(&csr[e + 1]) : -1;
        int i2 = (e + 2 < s1) ? __ldg(&csr[e + 2]) : -1;
        int i3 = (e + 3 < s1) ? __ldg(&csr[e + 3]) : -1;
        float2 v0 = (i0 >= 0) ? *(const float2*)(Xl + i0) : make_float2(0.f, 0.f);
        float2 v1 = (i1 >= 0) ? *(const float2*)(Xl + i1) : make_float2(0.f, 0.f);
        float2 v2 = (i2 >= 0) ? *(const float2*)(Xl + i2) : make_float2(0.f, 0.f);
        float2 v3 = (i3 >= 0) ? *(const float2*)(Xl + i3) : make_float2(0.f, 0.f);
        acc.x += (v0.x + v1.x) + (v2.x + v3.x);
        acc.y += (v0.y + v1.y) + (v2.y + v3.y);
    }
    float inv = 1.f / fmaxf((float)(s1 - s0), 1.f);
    acc.x *= inv; acc.y *= inv;
    *(float2*)&MEAN[(size_t)row * HDIM + lane * 2] = acc;
}

// ---------------------------------------------------------------------------
// Y = act( MEAN @ Wl.T + bl + Xin @ Wr.T )  — row-pair f32x2 GEMM.
// sInT [k][row] (stride 130): LDS.64 yields two rows packed.
// sW2  [k][2h + 2(h>>4)] (stride 136): each weight duplicated -> LDS.64 yields
// a pre-broadcast pair; swizzle term 2(h>>4) makes reads conflict-free.
// Inner loop per k per thread: 8 LDS.64 + 16 FFMA2, zero MOVs.
// Thread tile: 4 row-pairs (8 rows) x 4 cols; acc = 16 u64 = 32 regs.
// smem = 34.8 + 33.3 = 68.1 KB -> 3 blocks/SM.
// ---------------------------------------------------------------------------
#define SROW 130
#define WROW 136
#define RPB  128

__device__ __forceinline__ void accum_T(const float* __restrict__ sW2,
                                        const float* __restrict__ sInT,
                                        int wbase, int g2, u64 acc[4][4]) {
#pragma unroll 16
    for (int k = 0; k < 64; k++) {
        const float* wrow = sW2 + k * WROW + wbase;
        u64 w0 = *(const u64*)(wrow + 0);
        u64 w1 = *(const u64*)(wrow + 2);
        u64 w2 = *(const u64*)(wrow + 4);
        u64 w3 = *(const u64*)(wrow + 6);
        const float* vrow = sInT + k * SROW + 2 * g2;
#pragma unroll
        for (int p = 0; p < 4; p++) {
            u64 vv = *(const u64*)(vrow + 32 * p);
            acc[p][0] = ffma2(vv, w0, acc[p][0]);
            acc[p][1] = ffma2(vv, w1, acc[p][1]);
            acc[p][2] = ffma2(vv, w2, acc[p][2]);
            acc[p][3] = ffma2(vv, w3, acc[p][3]);
        }
    }
}

// conflict-free transposed tile loader: i -> (k16, r) bijection
__device__ __forceinline__ void load_tileT(const float* __restrict__ SRC,
                                           int base, float* __restrict__ sInT,
                                           int tid) {
    for (int i = tid; i < RPB * 16; i += 256) {
        int lo2 = i & 3, hi2 = (i >> 9) & 3;
        int r   = (i >> 2) & 127;
        int k4  = (lo2 + 4 * hi2) * 4;
        int row = base + r;
        float4 v = make_float4(0.f, 0.f, 0.f, 0.f);
        if (row < NN) v = *(const float4*)&SRC[(size_t)row * HDIM + k4];
        sInT[(k4 + 0) * SROW + r] = v.x;
        sInT[(k4 + 1) * SROW + r] = v.y;
        sInT[(k4 + 2) * SROW + r] = v.z;
        sInT[(k4 + 3) * SROW + r] = v.w;
    }
}

__device__ __forceinline__ void load_weightsT(const float* __restrict__ W,
                                              float* __restrict__ sW2, int tid) {
    for (int i = tid; i < 64 * 64; i += 256) {
        int h = i >> 6, k = i & 63;
        float w = W[i];
        int pos = k * WROW + 2 * h + 2 * (h >> 4);
        sW2[pos]     = w;
        sW2[pos + 1] = w;
    }
}

template <bool RELU>
__global__ void __launch_bounds__(256, 3)
combine_kernel(const float* __restrict__ Xin, const float* __restrict__ MEAN,
               const float* __restrict__ Wl, const float* __restrict__ bl,
               const float* __restrict__ Wr, float* __restrict__ Y) {
    extern __shared__ float smem[];
    float* sW2  = smem;                 // [64][WROW]
    float* sInT = smem + 64 * WROW;     // [64][SROW]
    __shared__ float sb[64];

    int tid  = threadIdx.x;
    int base = blockIdx.x * RPB;
    int c    = tid & 15;                // col group: h0 = 4c
    int g2   = tid >> 4;                // row-pair group 0..15
    int wbase = 8 * c + 2 * (c >> 2);   // swizzled weight offset

    // phase-1: Wl + MEAN tile
    load_weightsT(Wl, sW2, tid);
    if (tid < 64) sb[tid] = bl[tid];
    load_tileT(MEAN, base, sInT, tid);
    __syncthreads();

    u64 acc[4][4];
    {
        int h0 = 4 * c;
        u64 b0 = pack2(sb[h0],     sb[h0]);
        u64 b1 = pack2(sb[h0 + 1], sb[h0 + 1]);
        u64 b2 = pack2(sb[h0 + 2], sb[h0 + 2]);
        u64 b3 = pack2(sb[h0 + 3], sb[h0 + 3]);
#pragma unroll
        for (int p = 0; p < 4; p++) {
            acc[p][0] = b0; acc[p][1] = b1; acc[p][2] = b2; acc[p][3] = b3;
        }
    }

    accum_T(sW2, sInT, wbase, g2, acc);   // mean @ Wl^T
    __syncthreads();

    // phase-2: Wr + X tile
    load_weightsT(Wr, sW2, tid);
    load_tileT(Xin, base, sInT, tid);
    __syncthreads();

    accum_T(sW2, sInT, wbase, g2, acc);   // + x @ Wr^T

    int h0 = 4 * c;
#pragma unroll
    for (int p = 0; p < 4; p++) {
        int rA = base + 2 * (g2 + 16 * p);
        int rB = rA + 1;
        float2 q0 = unpack2(acc[p][0]);
        float2 q1 = unpack2(acc[p][1]);
        float2 q2 = unpack2(acc[p][2]);
        float2 q3 = unpack2(acc[p][3]);
        float4 oA = make_float4(q0.x, q1.x, q2.x, q3.x);
        float4 oB = make_float4(q0.y, q1.y, q2.y, q3.y);
        if (RELU) {
            oA.x = fmaxf(oA.x, 0.f); oA.y = fmaxf(oA.y, 0.f);
            oA.z = fmaxf(oA.z, 0.f); oA.w = fmaxf(oA.w, 0.f);
            oB.x = fmaxf(oB.x, 0.f); oB.y = fmaxf(oB.y, 0.f);
            oB.z = fmaxf(oB.z, 0.f); oB.w = fmaxf(oB.w, 0.f);
        }
        if (rA < NN) *(float4*)&Y[(size_t)rA * HDIM + h0] = oA;
        if (rB < NN) *(float4*)&Y[(size_t)rB * HDIM + h0] = oB;
    }
}

// ---------------------------------------------------------------------------
// out[e] = dot(Z[u[e]], Z[N_USERS + m[e]]) — 16 lanes per label edge, float4
// ---------------------------------------------------------------------------
__global__ void dot_kernel(const int* __restrict__ eli,
                           const float* __restrict__ Z,
                           float* __restrict__ out) {
    int gw = (blockIdx.x * blockDim.x + threadIdx.x) >> 4;
    int l  = threadIdx.x & 15;
    if (gw >= NEL) return;
    int u = __ldg(&eli[gw]);
    int m = __ldg(&eli[NEL + gw]);
    float4 a = *(const float4*)&Z[(size_t)u * HDIM + l * 4];
    float4 b = *(const float4*)&Z[(size_t)(N_USERS + m) * HDIM + l * 4];
    float s = a.x * b.x + a.y * b.y + a.z * b.z + a.w * b.w;
#pragma unroll
    for (int o = 8; o; o >>= 1) s += __shfl_xor_sync(0xffffffffu, s, o);
    if (l == 0) out[gw] = s;
}

// ---------------------------------------------------------------------------
extern "C" void kernel_launch(void* const* d_in, const int* in_sizes, int n_in,
                              void* d_out, int out_size) {
    const float* movie_x   = (const float*)d_in[0];
    const float* user_emb  = (const float*)d_in[1];
    const float* movie_emb = (const float*)d_in[2];
    const float* lin_W     = (const float*)d_in[3];
    const float* lin_b     = (const float*)d_in[4];
    const float* W1l       = (const float*)d_in[5];
    const float* b1        = (const float*)d_in[6];
    const float* W1r       = (const float*)d_in[7];
    const float* W2l       = (const float*)d_in[8];
    const float* b2        = (const float*)d_in[9];
    const float* W2r       = (const float*)d_in[10];
    const int*   ei        = (const int*)d_in[11];
    const int*   eli       = (const int*)d_in[12];
    float* out = (float*)d_out;

    float *dX, *dY, *dZ, *dM;
    int *dDEGI, *dOFF, *dCUR, *dCSR, *dPREF, *dFLAG;
    cudaGetSymbolAddress((void**)&dX,    g_X);
    cudaGetSymbolAddress((void**)&dY,    g_Y);
    cudaGetSymbolAddress((void**)&dZ,    g_Z);
    cudaGetSymbolAddress((void**)&dM,    g_M);
    cudaGetSymbolAddress((void**)&dDEGI, g_DEGI);
    cudaGetSymbolAddress((void**)&dOFF,  g_OFF);
    cudaGetSymbolAddress((void**)&dCUR,  g_CUR);
    cudaGetSymbolAddress((void**)&dCSR,  g_CSR);
    cudaGetSymbolAddress((void**)&dPREF, g_PREF);
    cudaGetSymbolAddress((void**)&dFLAG, g_FLAG);

    const size_t smemC = (size_t)(64 * WROW + 64 * SROW) * sizeof(float); // 68.1 KB
    cudaFuncSetAttribute(combine_kernel<true>,
                         cudaFuncAttributeMaxDynamicSharedMemorySize, (int)smemC);
    cudaFuncSetAttribute(combine_kernel<false>,
                         cudaFuncAttributeMaxDynamicSharedMemorySize, (int)smemC);

    const int gridC = (NN + RPB - 1) / RPB;   // 2188
    const int gridG = (NN * 32 + 255) / 256;  // warp per row
    const int gridI = (NN + 3) / 4;           // init+hist (covers NE too)

    // ---- prologue: features + CSR ----
    cudaMemsetAsync(dDEGI, 0, NN * sizeof(int));
    init_hist_kernel<<<gridI, 256>>>(ei, dDEGI, dFLAG, movie_x, user_emb,
                                     movie_emb, lin_W, lin_b, dX);          // #1
    scan_chain_kernel<<<NB2, 256>>>(dDEGI, dOFF, dCUR, dPREF, dFLAG);       // #2
    fill_kernel<<<(NE + 255) / 256, 256>>>(ei, dCUR, dCSR);                 // #3

    // ---- layer 1 ----
    gather_kernel<<<gridG, 256>>>(dX, dOFF, dCSR, dM);                      // #4 (profiled)
    combine_kernel<true><<<gridC, 256, smemC>>>(dX, dM, W1l, b1, W1r, dY);  // #5

    // ---- layer 2 ----
    gather_kernel<<<gridG, 256>>>(dY, dOFF, dCSR, dM);                      // #6
    combine_kernel<false><<<gridC, 256, smemC>>>(dY, dM, W2l, b2, W2r, dZ); // #7

    // ---- decode ----
    dot_kernel<<<(NEL * 16) / 256, 256>>>(eli, dZ, out);                    // #8
}

// round 10
// speedup vs baseline: 1.1232x; 1.0544x over previous
#include <cuda_runtime.h>
#include <cstddef>

#define N_USERS 200000
#define N_MOVIES 80000
#define NN 280000
#define HDIM 64
#define F_MOVIE 20
#define NE 1250000
#define NEL 500000
#define NB2 274           // ceil(NN / 1024)

typedef unsigned long long u64;

// Scratch (static device globals: allowed; runtime allocation is not).
__device__ __align__(16) float g_X[(size_t)NN * HDIM];
__device__ __align__(16) float g_Y[(size_t)NN * HDIM];
__device__ __align__(16) float g_Z[(size_t)NN * HDIM];
__device__ __align__(16) float g_M[(size_t)NN * HDIM];
__device__ int g_DEGI[NN];
__device__ int g_OFF[NN + 1];
__device__ int g_CUR[NN];
__device__ int g_CSR[NE];      // holds src*HDIM (premultiplied)
__device__ int g_PREF[NB2];
__device__ int g_FLAG[NB2];

// ---- packed f32x2 helpers (Blackwell FFMA2 path, PTX-only) -----------------
__device__ __forceinline__ u64 pack2(float lo, float hi) {
    u64 r; asm("mov.b64 %0, {%1, %2};" : "=l"(r) : "f"(lo), "f"(hi)); return r;
}
__device__ __forceinline__ u64 bcast2(float x) {
    u64 r; asm("mov.b64 %0, {%1, %1};" : "=l"(r) : "f"(x)); return r;
}
__device__ __forceinline__ u64 ffma2(u64 a, u64 b, u64 c) {
    u64 d; asm("fma.rn.f32x2 %0, %1, %2, %3;" : "=l"(d) : "l"(a), "l"(b), "l"(c));
    return d;
}
__device__ __forceinline__ float2 unpack2(u64 v) {
    float2 f; asm("mov.b64 {%0, %1}, %2;" : "=f"(f.x), "=f"(f.y) : "l"(v)); return f;
}

// ---------------------------------------------------------------------------
// 1) fused: X init (row-parallel) + degree histogram (edge-parallel) + flag zero
// ---------------------------------------------------------------------------
__global__ void init_hist_kernel(const int* __restrict__ ei,
                                 int* __restrict__ degi, int* __restrict__ flag,
                                 const float* __restrict__ movie_x,
                                 const float* __restrict__ user_emb,
                                 const float* __restrict__ movie_emb,
                                 const float* __restrict__ lin_W,
                                 const float* __restrict__ lin_b,
                                 float* __restrict__ X) {
    int gid = blockIdx.x * blockDim.x + threadIdx.x;
    if (gid < NE) atomicAdd(&degi[ei[NE + gid]], 1);
    if (gid < NB2) flag[gid] = 0;

    __shared__ float sx[4][F_MOVIE];
    int lr  = threadIdx.x >> 6;
    int h   = threadIdx.x & 63;
    int row = blockIdx.x * 4 + lr;
    int mrow = row - N_USERS;
    if (row < NN && mrow >= 0 && h < F_MOVIE)
        sx[lr][h] = movie_x[mrow * F_MOVIE + h];
    __syncthreads();
    if (row >= NN) return;
    if (mrow < 0) {
        X[(size_t)row * HDIM + h] = user_emb[(size_t)row * HDIM + h];
    } else {
        float acc = lin_b[h] + movie_emb[(size_t)mrow * HDIM + h];
#pragma unroll
        for (int f = 0; f < F_MOVIE; f++)
            acc += sx[lr][f] * lin_W[h * F_MOVIE + f];
        X[(size_t)row * HDIM + h] = acc;
    }
}

// ---------------------------------------------------------------------------
// 2) single-pass chained exclusive scan of degi -> off, cur (274 co-resident blocks)
// ---------------------------------------------------------------------------
__global__ void scan_chain_kernel(const int* __restrict__ degi,
                                  int* __restrict__ off, int* __restrict__ cur,
                                  volatile int* __restrict__ pref,
                                  volatile int* __restrict__ flag) {
    __shared__ int ss[256];
    __shared__ int s_prefix;
    int b = blockIdx.x, t = threadIdx.x;
    int i0 = b * 1024 + t * 4;
    int v[4];
    int tot = 0;
#pragma unroll
    for (int j = 0; j < 4; j++) {
        int i = i0 + j;
        v[j] = (i < NN) ? degi[i] : 0;
        tot += v[j];
    }
    ss[t] = tot;
    __syncthreads();
#pragma unroll
    for (int o = 1; o < 256; o <<= 1) {
        int x = (t >= o) ? ss[t - o] : 0;
        __syncthreads();
        ss[t] += x;
        __syncthreads();
    }
    if (t == 0) {
        int p = 0;
        if (b > 0) {
            while (flag[b - 1] == 0) { }
            __threadfence();
            p = pref[b - 1];
        }
        pref[b] = p + ss[255];
        __threadfence();
        flag[b] = 1;
        s_prefix = p;
        if (b == 0) off[NN] = NE;
    }
    __syncthreads();
    int run = s_prefix + ((t == 0) ? 0 : ss[t - 1]);
#pragma unroll
    for (int j = 0; j < 4; j++) {
        int i = i0 + j;
        if (i < NN) { off[i] = run; cur[i] = run; }
        run += v[j];
    }
}

// ---------------------------------------------------------------------------
// 3) CSR fill — stores src*HDIM so gather needs no multiply
// ---------------------------------------------------------------------------
__global__ void fill_kernel(const int* __restrict__ ei,
                            int* __restrict__ cur, int* __restrict__ csr) {
    int e = blockIdx.x * blockDim.x + threadIdx.x;
    if (e >= NE) return;
    int src = ei[e];
    int dst = ei[NE + e];
    int p = atomicAdd(&cur[dst], 1);
    csr[p] = src * HDIM;
}

// ---------------------------------------------------------------------------
// 4) MEAN[row] = mean over neighbors — warp per row, float2 lanes, MLP=4,
//    premultiplied csr indices.
// ---------------------------------------------------------------------------
__global__ void __launch_bounds__(256)
gather_kernel(const float* __restrict__ Xin,
              const int* __restrict__ off, const int* __restrict__ csr,
              float* __restrict__ MEAN) {
    int row  = (blockIdx.x * blockDim.x + threadIdx.x) >> 5;
    int lane = threadIdx.x & 31;
    if (row >= NN) return;
    int s0 = __ldg(&off[row]);
    int s1 = __ldg(&off[row + 1]);
    const float* Xl = Xin + lane * 2;
    float2 acc = make_float2(0.f, 0.f);
    for (int e = s0; e < s1; e += 4) {
        int i0 = (e     < s1) ? __ldg(&csr[e])     : -1;
        int i1 = (e + 1 < s1) ? __ldg(&csr[e + 1]) : -1;
        int i2 = (e + 2 < s1) ? __ldg(&csr[e + 2]) : -1;
        int i3 = (e + 3 < s1) ? __ldg(&csr[e + 3]) : -1;
        float2 v0 = (i0 >= 0) ? *(const float2*)(Xl + i0) : make_float2(0.f, 0.f);
        float2 v1 = (i1 >= 0) ? *(const float2*)(Xl + i1) : make_float2(0.f, 0.f);
        float2 v2 = (i2 >= 0) ? *(const float2*)(Xl + i2) : make_float2(0.f, 0.f);
        float2 v3 = (i3 >= 0) ? *(const float2*)(Xl + i3) : make_float2(0.f, 0.f);
        acc.x += (v0.x + v1.x) + (v2.x + v3.x);
        acc.y += (v0.y + v1.y) + (v2.y + v3.y);
    }
    float inv = 1.f / fmaxf((float)(s1 - s0), 1.f);
    acc.x *= inv; acc.y *= inv;
    *(float2*)&MEAN[(size_t)row * HDIM + lane * 2] = acc;
}

// ---------------------------------------------------------------------------
// Y = act( MEAN @ Wl.T + bl + Xin @ Wr.T )  — proven R7 GEMM shape.
// 256 threads, 128x64 tile, 8x4 thread tile, FFMA2, phased weights.
// Weight LDS.128: 16 distinct addrs/warp (2-lane bcast). Input LDS.128:
// 2 distinct addrs/warp (16-lane bcast, ~free). 52.2 KB smem -> 4 blocks/SM.
// ---------------------------------------------------------------------------
#define WPAD 68
#define RPB  128

__device__ __forceinline__ void accum_phase(const float* __restrict__ sW,
                                            const float* __restrict__ sIn,
                                            int h0, int r0, u64 acc[8][2]) {
#pragma unroll
    for (int k = 0; k < 64; k += 4) {
        ulonglong2 w[4];
#pragma unroll
        for (int kk = 0; kk < 4; kk++)
            w[kk] = *(const ulonglong2*)&sW[(k + kk) * WPAD + h0];
#pragma unroll
        for (int i = 0; i < 8; i++) {
            float4 v = *(const float4*)&sIn[(r0 + i) * WPAD + k];
            u64 t;
            t = bcast2(v.x); acc[i][0] = ffma2(t, w[0].x, acc[i][0]);
                             acc[i][1] = ffma2(t, w[0].y, acc[i][1]);
            t = bcast2(v.y); acc[i][0] = ffma2(t, w[1].x, acc[i][0]);
                             acc[i][1] = ffma2(t, w[1].y, acc[i][1]);
            t = bcast2(v.z); acc[i][0] = ffma2(t, w[2].x, acc[i][0]);
                             acc[i][1] = ffma2(t, w[2].y, acc[i][1]);
            t = bcast2(v.w); acc[i][0] = ffma2(t, w[3].x, acc[i][0]);
                             acc[i][1] = ffma2(t, w[3].y, acc[i][1]);
        }
    }
}

template <bool RELU>
__global__ void __launch_bounds__(256, 4)
combine_kernel(const float* __restrict__ Xin, const float* __restrict__ MEAN,
               const float* __restrict__ Wl, const float* __restrict__ bl,
               const float* __restrict__ Wr, float* __restrict__ Y) {
    extern __shared__ float smem[];
    float* sW  = smem;               // [64][WPAD]
    float* sIn = smem + 64 * WPAD;   // [128][WPAD]
    __shared__ float sb[64];

    int tid  = threadIdx.x;
    int base = blockIdx.x * RPB;

    // phase-1: Wl^T + MEAN tile
    for (int i = tid; i < 64 * 64; i += 256) {
        int h = i >> 6, k = i & 63;
        sW[k * WPAD + h] = Wl[i];
    }
    if (tid < 64) sb[tid] = bl[tid];
    for (int i = tid; i < RPB * 16; i += 256) {
        int r = i >> 4, k4 = (i & 15) * 4;
        int row = base + r;
        float4 v = make_float4(0.f, 0.f, 0.f, 0.f);
        if (row < NN) v = *(const float4*)&MEAN[(size_t)row * HDIM + k4];
        *(float4*)&sIn[r * WPAD + k4] = v;
    }
    __syncthreads();

    int h0 = (tid & 15) * 4;
    int r0 = (tid >> 4) * 8;

    u64 acc[8][2];
    {
        u64 b01 = pack2(sb[h0], sb[h0 + 1]);
        u64 b23 = pack2(sb[h0 + 2], sb[h0 + 3]);
#pragma unroll
        for (int i = 0; i < 8; i++) { acc[i][0] = b01; acc[i][1] = b23; }
    }

    accum_phase(sW, sIn, h0, r0, acc);      // mean @ Wl^T
    __syncthreads();

    // phase-2: Wr^T + x tile
    for (int i = tid; i < 64 * 64; i += 256) {
        int h = i >> 6, k = i & 63;
        sW[k * WPAD + h] = Wr[i];
    }
    for (int i = tid; i < RPB * 16; i += 256) {
        int r = i >> 4, k4 = (i & 15) * 4;
        int row = base + r;
        float4 v = make_float4(0.f, 0.f, 0.f, 0.f);
        if (row < NN) v = *(const float4*)&Xin[(size_t)row * HDIM + k4];
        *(float4*)&sIn[r * WPAD + k4] = v;
    }
    __syncthreads();

    accum_phase(sW, sIn, h0, r0, acc);      // + x @ Wr^T

#pragma unroll
    for (int i = 0; i < 8; i++) {
        int row = base + r0 + i;
        if (row >= NN) break;
        float2 lo = unpack2(acc[i][0]);
        float2 hi = unpack2(acc[i][1]);
        float4 o;
        o.x = lo.x; o.y = lo.y; o.z = hi.x; o.w = hi.y;
        if (RELU) {
            o.x = fmaxf(o.x, 0.f); o.y = fmaxf(o.y, 0.f);
            o.z = fmaxf(o.z, 0.f); o.w = fmaxf(o.w, 0.f);
        }
        *(float4*)&Y[(size_t)row * HDIM + h0] = o;
    }
}

// ---------------------------------------------------------------------------
// out[e] = dot(Z[u[e]], Z[N_USERS + m[e]]) — 16 lanes per label edge, float4
// ---------------------------------------------------------------------------
__global__ void dot_kernel(const int* __restrict__ eli,
                           const float* __restrict__ Z,
                           float* __restrict__ out) {
    int gw = (blockIdx.x * blockDim.x + threadIdx.x) >> 4;
    int l  = threadIdx.x & 15;
    if (gw >= NEL) return;
    int u = __ldg(&eli[gw]);
    int m = __ldg(&eli[NEL + gw]);
    float4 a = *(const float4*)&Z[(size_t)u * HDIM + l * 4];
    float4 b = *(const float4*)&Z[(size_t)(N_USERS + m) * HDIM + l * 4];
    float s = a.x * b.x + a.y * b.y + a.z * b.z + a.w * b.w;
#pragma unroll
    for (int o = 8; o; o >>= 1) s += __shfl_xor_sync(0xffffffffu, s, o);
    if (l == 0) out[gw] = s;
}

// ---------------------------------------------------------------------------
extern "C" void kernel_launch(void* const* d_in, const int* in_sizes, int n_in,
                              void* d_out, int out_size) {
    const float* movie_x   = (const float*)d_in[0];
    const float* user_emb  = (const float*)d_in[1];
    const float* movie_emb = (const float*)d_in[2];
    const float* lin_W     = (const float*)d_in[3];
    const float* lin_b     = (const float*)d_in[4];
    const float* W1l       = (const float*)d_in[5];
    const float* b1        = (const float*)d_in[6];
    const float* W1r       = (const float*)d_in[7];
    const float* W2l       = (const float*)d_in[8];
    const float* b2        = (const float*)d_in[9];
    const float* W2r       = (const float*)d_in[10];
    const int*   ei        = (const int*)d_in[11];
    const int*   eli       = (const int*)d_in[12];
    float* out = (float*)d_out;

    float *dX, *dY, *dZ, *dM;
    int *dDEGI, *dOFF, *dCUR, *dCSR, *dPREF, *dFLAG;
    cudaGetSymbolAddress((void**)&dX,    g_X);
    cudaGetSymbolAddress((void**)&dY,    g_Y);
    cudaGetSymbolAddress((void**)&dZ,    g_Z);
    cudaGetSymbolAddress((void**)&dM,    g_M);
    cudaGetSymbolAddress((void**)&dDEGI, g_DEGI);
    cudaGetSymbolAddress((void**)&dOFF,  g_OFF);
    cudaGetSymbolAddress((void**)&dCUR,  g_CUR);
    cudaGetSymbolAddress((void**)&dCSR,  g_CSR);
    cudaGetSymbolAddress((void**)&dPREF, g_PREF);
    cudaGetSymbolAddress((void**)&dFLAG, g_FLAG);

    const size_t smemC = (size_t)((64 + RPB) * WPAD) * sizeof(float); // 52.2 KB
    cudaFuncSetAttribute(combine_kernel<true>,
                         cudaFuncAttributeMaxDynamicSharedMemorySize, (int)smemC);
    cudaFuncSetAttribute(combine_kernel<false>,
                         cudaFuncAttributeMaxDynamicSharedMemorySize, (int)smemC);

    const int gridC = (NN + RPB - 1) / RPB;   // 2188
    const int gridG = (NN * 32 + 255) / 256;  // warp per row
    const int gridI = (NN + 3) / 4;           // init+hist (covers NE too)

    // ---- prologue: features + CSR ----
    cudaMemsetAsync(dDEGI, 0, NN * sizeof(int));
    init_hist_kernel<<<gridI, 256>>>(ei, dDEGI, dFLAG, movie_x, user_emb,
                                     movie_emb, lin_W, lin_b, dX);          // #1
    scan_chain_kernel<<<NB2, 256>>>(dDEGI, dOFF, dCUR, dPREF, dFLAG);       // #2
    fill_kernel<<<(NE + 255) / 256, 256>>>(ei, dCUR, dCSR);                 // #3

    // ---- layer 1 ----
    gather_kernel<<<gridG, 256>>>(dX, dOFF, dCSR, dM);                      // #4 (profiled)
    combine_kernel<true><<<gridC, 256, smemC>>>(dX, dM, W1l, b1, W1r, dY);  // #5

    // ---- layer 2 ----
    gather_kernel<<<gridG, 256>>>(dY, dOFF, dCSR, dM);                      // #6
    combine_kernel<false><<<gridC, 256, smemC>>>(dY, dM, W2l, b2, W2r, dZ); // #7

    // ---- decode ----
    dot_kernel<<<(NEL * 16) / 256, 256>>>(eli, dZ, out);                    // #8
}

// round 11
// speedup vs baseline: 1.8108x; 1.6123x over previous
#include <cuda_runtime.h>
#include <cstddef>

#define N_USERS 200000
#define N_MOVIES 80000
#define NN 280000
#define HDIM 64
#define F_MOVIE 20
#define NE 1250000
#define NEL 500000
#define NB2 274           // ceil(NN / 1024)

typedef unsigned long long u64;

// Scratch (static device globals: allowed; runtime allocation is not).
__device__ __align__(16) float g_X[(size_t)NN * HDIM];
__device__ __align__(16) float g_Y[(size_t)NN * HDIM];
__device__ __align__(16) float g_Z[(size_t)NN * HDIM];
__device__ __align__(16) float g_M[(size_t)NN * HDIM];
__device__ int g_DEGI[NN];
__device__ int g_OFF[NN + 1];
__device__ int g_CUR[NN];
__device__ int g_CSR[NE];      // holds src*HDIM (premultiplied)
__device__ int g_BSUM[512];

// ---- packed f32x2 helpers (Blackwell FFMA2 path, PTX-only) -----------------
__device__ __forceinline__ u64 pack2(float lo, float hi) {
    u64 r; asm("mov.b64 %0, {%1, %2};" : "=l"(r) : "f"(lo), "f"(hi)); return r;
}
__device__ __forceinline__ u64 bcast2(float x) {
    u64 r; asm("mov.b64 %0, {%1, %1};" : "=l"(r) : "f"(x)); return r;
}
__device__ __forceinline__ u64 ffma2(u64 a, u64 b, u64 c) {
    u64 d; asm("fma.rn.f32x2 %0, %1, %2, %3;" : "=l"(d) : "l"(a), "l"(b), "l"(c));
    return d;
}
__device__ __forceinline__ float2 unpack2(u64 v) {
    float2 f; asm("mov.b64 {%0, %1}, %2;" : "=f"(f.x), "=f"(f.y) : "l"(v)); return f;
}

// ---------------------------------------------------------------------------
// 1) fused: X init (row-parallel) + degree histogram (edge-parallel)
// ---------------------------------------------------------------------------
__global__ void init_hist_kernel(const int* __restrict__ ei,
                                 int* __restrict__ degi,
                                 const float* __restrict__ movie_x,
                                 const float* __restrict__ user_emb,
                                 const float* __restrict__ movie_emb,
                                 const float* __restrict__ lin_W,
                                 const float* __restrict__ lin_b,
                                 float* __restrict__ X) {
    int gid = blockIdx.x * blockDim.x + threadIdx.x;
    if (gid < NE) atomicAdd(&degi[ei[NE + gid]], 1);

    __shared__ float sx[4][F_MOVIE];
    int lr  = threadIdx.x >> 6;
    int h   = threadIdx.x & 63;
    int row = blockIdx.x * 4 + lr;
    int mrow = row - N_USERS;
    if (row < NN && mrow >= 0 && h < F_MOVIE)
        sx[lr][h] = movie_x[mrow * F_MOVIE + h];
    __syncthreads();
    if (row >= NN) return;
    if (mrow < 0) {
        X[(size_t)row * HDIM + h] = user_emb[(size_t)row * HDIM + h];
    } else {
        float acc = lin_b[h] + movie_emb[(size_t)mrow * HDIM + h];
#pragma unroll
        for (int f = 0; f < F_MOVIE; f++)
            acc += sx[lr][f] * lin_W[h * F_MOVIE + f];
        X[(size_t)row * HDIM + h] = acc;
    }
}

// ---------------------------------------------------------------------------
// 2a) per-block sums of degi (1024 elements per block)
// ---------------------------------------------------------------------------
__global__ void scanA_kernel(const int* __restrict__ degi, int* __restrict__ bsum) {
    __shared__ int ws[8];
    int b = blockIdx.x, t = threadIdx.x;
    int i0 = b * 1024 + t * 4;
    int s = 0;
#pragma unroll
    for (int j = 0; j < 4; j++) { int i = i0 + j; s += (i < NN) ? degi[i] : 0; }
#pragma unroll
    for (int o = 16; o; o >>= 1) s += __shfl_xor_sync(0xffffffffu, s, o);
    if ((t & 31) == 0) ws[t >> 5] = s;
    __syncthreads();
    if (t == 0) {
        int tot = 0;
#pragma unroll
        for (int w = 0; w < 8; w++) tot += ws[w];
        bsum[b] = tot;
    }
}

// ---------------------------------------------------------------------------
// 2b) exclusive scan of the 274 block sums (single block)
// ---------------------------------------------------------------------------
__global__ void scanB_kernel(int* __restrict__ bsum, int* __restrict__ off) {
    __shared__ int s[512];
    int t = threadIdx.x;
    s[t] = (t < NB2) ? bsum[t] : 0;
    __syncthreads();
#pragma unroll
    for (int o = 1; o < 512; o <<= 1) {
        int x = (t >= o) ? s[t - o] : 0;
        __syncthreads();
        s[t] += x;
        __syncthreads();
    }
    int excl = (t == 0) ? 0 : s[t - 1];
    if (t < NB2) bsum[t] = excl;
    if (t == 0) off[NN] = NE;
}

// ---------------------------------------------------------------------------
// 2c) local scan + add block prefix -> off, cur
// ---------------------------------------------------------------------------
__global__ void scanC_kernel(const int* __restrict__ degi,
                             const int* __restrict__ boff,
                             int* __restrict__ off, int* __restrict__ cur) {
    __shared__ int ss[256];
    int b = blockIdx.x, t = threadIdx.x;
    int i0 = b * 1024 + t * 4;
    int v[4];
    int tot = 0;
#pragma unroll
    for (int j = 0; j < 4; j++) {
        int i = i0 + j;
        v[j] = (i < NN) ? degi[i] : 0;
        tot += v[j];
    }
    ss[t] = tot;
    __syncthreads();
#pragma unroll
    for (int o = 1; o < 256; o <<= 1) {
        int x = (t >= o) ? ss[t - o] : 0;
        __syncthreads();
        ss[t] += x;
        __syncthreads();
    }
    int run = boff[b] + ((t == 0) ? 0 : ss[t - 1]);
#pragma unroll
    for (int j = 0; j < 4; j++) {
        int i = i0 + j;
        if (i < NN) { off[i] = run; cur[i] = run; }
        run += v[j];
    }
}

// ---------------------------------------------------------------------------
// 3) CSR fill — stores src*HDIM so gather needs no multiply
// ---------------------------------------------------------------------------
__global__ void fill_kernel(const int* __restrict__ ei,
                            int* __restrict__ cur, int* __restrict__ csr) {
    int e = blockIdx.x * blockDim.x + threadIdx.x;
    if (e >= NE) return;
    int src = ei[e];
    int dst = ei[NE + e];
    int p = atomicAdd(&cur[dst], 1);
    csr[p] = src * HDIM;
}

// ---------------------------------------------------------------------------
// 4) MEAN[row] = mean over neighbors — warp per row, float2 lanes, MLP=4,
//    premultiplied csr indices.
// ---------------------------------------------------------------------------
__global__ void __launch_bounds__(256)
gather_kernel(const float* __restrict__ Xin,
              const int* __restrict__ off, const int* __restrict__ csr,
              float* __restrict__ MEAN) {
    int row  = (blockIdx.x * blockDim.x + threadIdx.x) >> 5;
    int lane = threadIdx.x & 31;
    if (row >= NN) return;
    int s0 = __ldg(&off[row]);
    int s1 = __ldg(&off[row + 1]);
    const float* Xl = Xin + lane * 2;
    float2 acc = make_float2(0.f, 0.f);
    for (int e = s0; e < s1; e += 4) {
        int i0 = (e     < s1) ? __ldg(&csr[e])     : -1;
        int i1 = (e + 1 < s1) ? __ldg(&csr[e + 1]) : -1;
        int i2 = (e + 2 < s1) ? __ldg(&csr[e + 2]) : -1;
        int i3 = (e + 3 < s1) ? __ldg(&csr[e + 3]) : -1;
        float2 v0 = (i0 >= 0) ? *(const float2*)(Xl + i0) : make_float2(0.f, 0.f);
        float2 v1 = (i1 >= 0) ? *(const float2*)(Xl + i1) : make_float2(0.f, 0.f);
        float2 v2 = (i2 >= 0) ? *(const float2*)(Xl + i2) : make_float2(0.f, 0.f);
        float2 v3 = (i3 >= 0) ? *(const float2*)(Xl + i3) : make_float2(0.f, 0.f);
        acc.x += (v0.x + v1.x) + (v2.x + v3.x);
        acc.y += (v0.y + v1.y) + (v2.y + v3.y);
    }
    float inv = 1.f / fmaxf((float)(s1 - s0), 1.f);
    acc.x *= inv; acc.y *= inv;
    *(float2*)&MEAN[(size_t)row * HDIM + lane * 2] = acc;
}

// ---------------------------------------------------------------------------
// Y = act( MEAN @ Wl.T + bl + Xin @ Wr.T )  — proven R7 GEMM shape.
// 256 threads, 128x64 tile, 8x4 thread tile, FFMA2, phased weights.
// 52.2 KB smem -> 4 blocks/SM.
// ---------------------------------------------------------------------------
#define WPAD 68
#define RPB  128

__device__ __forceinline__ void accum_phase(const float* __restrict__ sW,
                                            const float* __restrict__ sIn,
                                            int h0, int r0, u64 acc[8][2]) {
#pragma unroll
    for (int k = 0; k < 64; k += 4) {
        ulonglong2 w[4];
#pragma unroll
        for (int kk = 0; kk < 4; kk++)
            w[kk] = *(const ulonglong2*)&sW[(k + kk) * WPAD + h0];
#pragma unroll
        for (int i = 0; i < 8; i++) {
            float4 v = *(const float4*)&sIn[(r0 + i) * WPAD + k];
            u64 t;
            t = bcast2(v.x); acc[i][0] = ffma2(t, w[0].x, acc[i][0]);
                             acc[i][1] = ffma2(t, w[0].y, acc[i][1]);
            t = bcast2(v.y); acc[i][0] = ffma2(t, w[1].x, acc[i][0]);
                             acc[i][1] = ffma2(t, w[1].y, acc[i][1]);
            t = bcast2(v.z); acc[i][0] = ffma2(t, w[2].x, acc[i][0]);
                             acc[i][1] = ffma2(t, w[2].y, acc[i][1]);
            t = bcast2(v.w); acc[i][0] = ffma2(t, w[3].x, acc[i][0]);
                             acc[i][1] = ffma2(t, w[3].y, acc[i][1]);
        }
    }
}

template <bool RELU>
__global__ void __launch_bounds__(256, 4)
combine_kernel(const float* __restrict__ Xin, const float* __restrict__ MEAN,
               const float* __restrict__ Wl, const float* __restrict__ bl,
               const float* __restrict__ Wr, float* __restrict__ Y) {
    extern __shared__ float smem[];
    float* sW  = smem;               // [64][WPAD]
    float* sIn = smem + 64 * WPAD;   // [128][WPAD]
    __shared__ float sb[64];

    int tid  = threadIdx.x;
    int base = blockIdx.x * RPB;

    // phase-1: Wl^T + MEAN tile
    for (int i = tid; i < 64 * 64; i += 256) {
        int h = i >> 6, k = i & 63;
        sW[k * WPAD + h] = Wl[i];
    }
    if (tid < 64) sb[tid] = bl[tid];
    for (int i = tid; i < RPB * 16; i += 256) {
        int r = i >> 4, k4 = (i & 15) * 4;
        int row = base + r;
        float4 v = make_float4(0.f, 0.f, 0.f, 0.f);
        if (row < NN) v = *(const float4*)&MEAN[(size_t)row * HDIM + k4];
        *(float4*)&sIn[r * WPAD + k4] = v;
    }
    __syncthreads();

    int h0 = (tid & 15) * 4;
    int r0 = (tid >> 4) * 8;

    u64 acc[8][2];
    {
        u64 b01 = pack2(sb[h0], sb[h0 + 1]);
        u64 b23 = pack2(sb[h0 + 2], sb[h0 + 3]);
#pragma unroll
        for (int i = 0; i < 8; i++) { acc[i][0] = b01; acc[i][1] = b23; }
    }

    accum_phase(sW, sIn, h0, r0, acc);      // mean @ Wl^T
    __syncthreads();

    // phase-2: Wr^T + x tile
    for (int i = tid; i < 64 * 64; i += 256) {
        int h = i >> 6, k = i & 63;
        sW[k * WPAD + h] = Wr[i];
    }
    for (int i = tid; i < RPB * 16; i += 256) {
        int r = i >> 4, k4 = (i & 15) * 4;
        int row = base + r;
        float4 v = make_float4(0.f, 0.f, 0.f, 0.f);
        if (row < NN) v = *(const float4*)&Xin[(size_t)row * HDIM + k4];
        *(float4*)&sIn[r * WPAD + k4] = v;
    }
    __syncthreads();

    accum_phase(sW, sIn, h0, r0, acc);      // + x @ Wr^T

#pragma unroll
    for (int i = 0; i < 8; i++) {
        int row = base + r0 + i;
        if (row >= NN) break;
        float2 lo = unpack2(acc[i][0]);
        float2 hi = unpack2(acc[i][1]);
        float4 o;
        o.x = lo.x; o.y = lo.y; o.z = hi.x; o.w = hi.y;
        if (RELU) {
            o.x = fmaxf(o.x, 0.f); o.y = fmaxf(o.y, 0.f);
            o.z = fmaxf(o.z, 0.f); o.w = fmaxf(o.w, 0.f);
        }
        *(float4*)&Y[(size_t)row * HDIM + h0] = o;
    }
}

// ---------------------------------------------------------------------------
// out[e] = dot(Z[u[e]], Z[N_USERS + m[e]]) — 16 lanes per label edge, float4
// ---------------------------------------------------------------------------
__global__ void dot_kernel(const int* __restrict__ eli,
                           const float* __restrict__ Z,
                           float* __restrict__ out) {
    int gw = (blockIdx.x * blockDim.x + threadIdx.x) >> 4;
    int l  = threadIdx.x & 15;
    if (gw >= NEL) return;
    int u = __ldg(&eli[gw]);
    int m = __ldg(&eli[NEL + gw]);
    float4 a = *(const float4*)&Z[(size_t)u * HDIM + l * 4];
    float4 b = *(const float4*)&Z[(size_t)(N_USERS + m) * HDIM + l * 4];
    float s = a.x * b.x + a.y * b.y + a.z * b.z + a.w * b.w;
#pragma unroll
    for (int o = 8; o; o >>= 1) s += __shfl_xor_sync(0xffffffffu, s, o);
    if (l == 0) out[gw] = s;
}

// ---------------------------------------------------------------------------
extern "C" void kernel_launch(void* const* d_in, const int* in_sizes, int n_in,
                              void* d_out, int out_size) {
    const float* movie_x   = (const float*)d_in[0];
    const float* user_emb  = (const float*)d_in[1];
    const float* movie_emb = (const float*)d_in[2];
    const float* lin_W     = (const float*)d_in[3];
    const float* lin_b     = (const float*)d_in[4];
    const float* W1l       = (const float*)d_in[5];
    const float* b1        = (const float*)d_in[6];
    const float* W1r       = (const float*)d_in[7];
    const float* W2l       = (const float*)d_in[8];
    const float* b2        = (const float*)d_in[9];
    const float* W2r       = (const float*)d_in[10];
    const int*   ei        = (const int*)d_in[11];
    const int*   eli       = (const int*)d_in[12];
    float* out = (float*)d_out;

    float *dX, *dY, *dZ, *dM;
    int *dDEGI, *dOFF, *dCUR, *dCSR, *dBSUM;
    cudaGetSymbolAddress((void**)&dX,    g_X);
    cudaGetSymbolAddress((void**)&dY,    g_Y);
    cudaGetSymbolAddress((void**)&dZ,    g_Z);
    cudaGetSymbolAddress((void**)&dM,    g_M);
    cudaGetSymbolAddress((void**)&dDEGI, g_DEGI);
    cudaGetSymbolAddress((void**)&dOFF,  g_OFF);
    cudaGetSymbolAddress((void**)&dCUR,  g_CUR);
    cudaGetSymbolAddress((void**)&dCSR,  g_CSR);
    cudaGetSymbolAddress((void**)&dBSUM, g_BSUM);

    const size_t smemC = (size_t)((64 + RPB) * WPAD) * sizeof(float); // 52.2 KB
    cudaFuncSetAttribute(combine_kernel<true>,
                         cudaFuncAttributeMaxDynamicSharedMemorySize, (int)smemC);
    cudaFuncSetAttribute(combine_kernel<false>,
                         cudaFuncAttributeMaxDynamicSharedMemorySize, (int)smemC);

    const int gridC = (NN + RPB - 1) / RPB;   // 2188
    const int gridG = (NN * 32 + 255) / 256;  // warp per row
    const int gridI = (NN + 3) / 4;           // init+hist (covers NE too)

    // ---- prologue: features + CSR (parallel 3-pass scan, no serial chain) ----
    cudaMemsetAsync(dDEGI, 0, NN * sizeof(int));
    init_hist_kernel<<<gridI, 256>>>(ei, dDEGI, movie_x, user_emb,
                                     movie_emb, lin_W, lin_b, dX);          // #1
    scanA_kernel<<<NB2, 256>>>(dDEGI, dBSUM);                               // #2
    scanB_kernel<<<1, 512>>>(dBSUM, dOFF);                                  // #3
    scanC_kernel<<<NB2, 256>>>(dDEGI, dBSUM, dOFF, dCUR);                   // #4
    fill_kernel<<<(NE + 255) / 256, 256>>>(ei, dCUR, dCSR);                 // #5

    // ---- layer 1 ----
    gather_kernel<<<gridG, 256>>>(dX, dOFF, dCSR, dM);                      // #6
    combine_kernel<true><<<gridC, 256, smemC>>>(dX, dM, W1l, b1, W1r, dY);  // #7

    // ---- layer 2 ----
    gather_kernel<<<gridG, 256>>>(dY, dOFF, dCSR, dM);                      // #8
    combine_kernel<false><<<gridC, 256, smemC>>>(dY, dM, W2l, b2, W2r, dZ); // #9

    // ---- decode ----
    dot_kernel<<<(NEL * 16) / 256, 256>>>(eli, dZ, out);                    // #10
}

// round 12
// speedup vs baseline: 2.4181x; 1.3353x over previous
#include <cuda_runtime.h>
#include <cstddef>
#include <cstdint>

#define N_USERS 200000
#define N_MOVIES 80000
#define NN 280000
#define HDIM 64
#define F_MOVIE 20
#define NE 1250000
#define NEL 500000
#define NB2 274           // ceil(NN / 1024)
#define BK 72             // bf16 row stride (144 bytes) for MMA smem tiles

typedef unsigned long long u64;

// Scratch (static device globals: allowed; runtime allocation is not).
__device__ __align__(16) float g_X[(size_t)NN * HDIM];
__device__ __align__(16) float g_Y[(size_t)NN * HDIM];
__device__ __align__(16) float g_Z[(size_t)NN * HDIM];
__device__ __align__(16) float g_M[(size_t)NN * HDIM];
__device__ int g_DEGI[NN];
__device__ int g_OFF[NN + 1];
__device__ int g_CUR[NN];
__device__ int g_CSR[NE];      // holds src*HDIM (premultiplied)
__device__ int g_BSUM[512];

__device__ __forceinline__ uint32_t smem_u32(const void* p) {
    return (uint32_t)__cvta_generic_to_shared(p);
}

#define LDSM4(d, addr) \
    asm volatile("ldmatrix.sync.aligned.m8n8.x4.shared.b16 {%0,%1,%2,%3}, [%4];" \
                 : "=r"((d)[0]), "=r"((d)[1]), "=r"((d)[2]), "=r"((d)[3]) \
                 : "r"(addr))

#define MMA16816(acc, a, b0v, b1v) \
    asm volatile("mma.sync.aligned.m16n8k16.row.col.f32.bf16.bf16.f32 " \
                 "{%0,%1,%2,%3}, {%4,%5,%6,%7}, {%8,%9}, {%0,%1,%2,%3};" \
                 : "+f"((acc)[0]), "+f"((acc)[1]), "+f"((acc)[2]), "+f"((acc)[3]) \
                 : "r"((a)[0]), "r"((a)[1]), "r"((a)[2]), "r"((a)[3]), \
                   "r"(b0v), "r"(b1v))

// split x -> hi (truncated bf16) + lo (truncated bf16 of exact residual)
__device__ __forceinline__ void store_split(uint16_t* sh, uint16_t* sl,
                                            int off, float4 v) {
    uint32_t ux = __float_as_uint(v.x), uy = __float_as_uint(v.y);
    uint32_t uz = __float_as_uint(v.z), uw = __float_as_uint(v.w);
    float hx = __uint_as_float(ux & 0xFFFF0000u);
    float hy = __uint_as_float(uy & 0xFFFF0000u);
    float hz = __uint_as_float(uz & 0xFFFF0000u);
    float hw = __uint_as_float(uw & 0xFFFF0000u);
    uint32_t h01 = __byte_perm(ux, uy, 0x7632);
    uint32_t h23 = __byte_perm(uz, uw, 0x7632);
    uint32_t l01 = __byte_perm(__float_as_uint(v.x - hx),
                               __float_as_uint(v.y - hy), 0x7632);
    uint32_t l23 = __byte_perm(__float_as_uint(v.z - hz),
                               __float_as_uint(v.w - hw), 0x7632);
    *(uint32_t*)(sh + off)     = h01;
    *(uint32_t*)(sh + off + 2) = h23;
    *(uint32_t*)(sl + off)     = l01;
    *(uint32_t*)(sl + off + 2) = l23;
}

// ---------------------------------------------------------------------------
// 1) fused: X init (row-parallel) + degree histogram (edge-parallel)
// ---------------------------------------------------------------------------
__global__ void init_hist_kernel(const int* __restrict__ ei,
                                 int* __restrict__ degi,
                                 const float* __restrict__ movie_x,
                                 const float* __restrict__ user_emb,
                                 const float* __restrict__ movie_emb,
                                 const float* __restrict__ lin_W,
                                 const float* __restrict__ lin_b,
                                 float* __restrict__ X) {
    int gid = blockIdx.x * blockDim.x + threadIdx.x;
    if (gid < NE) atomicAdd(&degi[ei[NE + gid]], 1);

    __shared__ float sx[4][F_MOVIE];
    int lr  = threadIdx.x >> 6;
    int h   = threadIdx.x & 63;
    int row = blockIdx.x * 4 + lr;
    int mrow = row - N_USERS;
    if (row < NN && mrow >= 0 && h < F_MOVIE)
        sx[lr][h] = movie_x[mrow * F_MOVIE + h];
    __syncthreads();
    if (row >= NN) return;
    if (mrow < 0) {
        X[(size_t)row * HDIM + h] = user_emb[(size_t)row * HDIM + h];
    } else {
        float acc = lin_b[h] + movie_emb[(size_t)mrow * HDIM + h];
#pragma unroll
        for (int f = 0; f < F_MOVIE; f++)
            acc += sx[lr][f] * lin_W[h * F_MOVIE + f];
        X[(size_t)row * HDIM + h] = acc;
    }
}

// ---------------------------------------------------------------------------
// 2) parallel 3-pass exclusive scan (NO serial chain)
// ---------------------------------------------------------------------------
__global__ void scanA_kernel(const int* __restrict__ degi, int* __restrict__ bsum) {
    __shared__ int ws[8];
    int b = blockIdx.x, t = threadIdx.x;
    int i0 = b * 1024 + t * 4;
    int s = 0;
#pragma unroll
    for (int j = 0; j < 4; j++) { int i = i0 + j; s += (i < NN) ? degi[i] : 0; }
#pragma unroll
    for (int o = 16; o; o >>= 1) s += __shfl_xor_sync(0xffffffffu, s, o);
    if ((t & 31) == 0) ws[t >> 5] = s;
    __syncthreads();
    if (t == 0) {
        int tot = 0;
#pragma unroll
        for (int w = 0; w < 8; w++) tot += ws[w];
        bsum[b] = tot;
    }
}

__global__ void scanB_kernel(int* __restrict__ bsum, int* __restrict__ off) {
    __shared__ int s[512];
    int t = threadIdx.x;
    s[t] = (t < NB2) ? bsum[t] : 0;
    __syncthreads();
#pragma unroll
    for (int o = 1; o < 512; o <<= 1) {
        int x = (t >= o) ? s[t - o] : 0;
        __syncthreads();
        s[t] += x;
        __syncthreads();
    }
    int excl = (t == 0) ? 0 : s[t - 1];
    if (t < NB2) bsum[t] = excl;
    if (t == 0) off[NN] = NE;
}

__global__ void scanC_kernel(const int* __restrict__ degi,
                             const int* __restrict__ boff,
                             int* __restrict__ off, int* __restrict__ cur) {
    __shared__ int ss[256];
    int b = blockIdx.x, t = threadIdx.x;
    int i0 = b * 1024 + t * 4;
    int v[4];
    int tot = 0;
#pragma unroll
    for (int j = 0; j < 4; j++) {
        int i = i0 + j;
        v[j] = (i < NN) ? degi[i] : 0;
        tot += v[j];
    }
    ss[t] = tot;
    __syncthreads();
#pragma unroll
    for (int o = 1; o < 256; o <<= 1) {
        int x = (t >= o) ? ss[t - o] : 0;
        __syncthreads();
        ss[t] += x;
        __syncthreads();
    }
    int run = boff[b] + ((t == 0) ? 0 : ss[t - 1]);
#pragma unroll
    for (int j = 0; j < 4; j++) {
        int i = i0 + j;
        if (i < NN) { off[i] = run; cur[i] = run; }
        run += v[j];
    }
}

// ---------------------------------------------------------------------------
// 3) CSR fill — stores src*HDIM so gather needs no multiply
// ---------------------------------------------------------------------------
__global__ void fill_kernel(const int* __restrict__ ei,
                            int* __restrict__ cur, int* __restrict__ csr) {
    int e = blockIdx.x * blockDim.x + threadIdx.x;
    if (e >= NE) return;
    int src = ei[e];
    int dst = ei[NE + e];
    int p = atomicAdd(&cur[dst], 1);
    csr[p] = src * HDIM;
}

// ---------------------------------------------------------------------------
// 4) MEAN[row] = mean over neighbors — warp per row, float2 lanes, MLP=4
// ---------------------------------------------------------------------------
__global__ void __launch_bounds__(256)
gather_kernel(const float* __restrict__ Xin,
              const int* __restrict__ off, const int* __restrict__ csr,
              float* __restrict__ MEAN) {
    int row  = (blockIdx.x * blockDim.x + threadIdx.x) >> 5;
    int lane = threadIdx.x & 31;
    if (row >= NN) return;
    int s0 = __ldg(&off[row]);
    int s1 = __ldg(&off[row + 1]);
    const float* Xl = Xin + lane * 2;
    float2 acc = make_float2(0.f, 0.f);
    for (int e = s0; e < s1; e += 4) {
        int i0 = (e     < s1) ? __ldg(&csr[e])     : -1;
        int i1 = (e + 1 < s1) ? __ldg(&csr[e + 1]) : -1;
        int i2 = (e + 2 < s1) ? __ldg(&csr[e + 2]) : -1;
        int i3 = (e + 3 < s1) ? __ldg(&csr[e + 3]) : -1;
        float2 v0 = (i0 >= 0) ? *(const float2*)(Xl + i0) : make_float2(0.f, 0.f);
        float2 v1 = (i1 >= 0) ? *(const float2*)(Xl + i1) : make_float2(0.f, 0.f);
        float2 v2 = (i2 >= 0) ? *(const float2*)(Xl + i2) : make_float2(0.f, 0.f);
        float2 v3 = (i3 >= 0) ? *(const float2*)(Xl + i3) : make_float2(0.f, 0.f);
        acc.x += (v0.x + v1.x) + (v2.x + v3.x);
        acc.y += (v0.y + v1.y) + (v2.y + v3.y);
    }
    float inv = 1.f / fmaxf((float)(s1 - s0), 1.f);
    acc.x *= inv; acc.y *= inv;
    *(float2*)&MEAN[(size_t)row * HDIM + lane * 2] = acc;
}

// ---------------------------------------------------------------------------
// Y = act( MEAN @ Wl.T + bl + Xin @ Wr.T )  — tensor-core combine.
// bf16 2-term split (hi+lo, truncated), 3 MMAs (hh, hl, lh) per tile: error
// ~2^-16, far under the 1e-3 gate. Warp tile: 16 rows x 64 cols; K=64/phase,
// two phases (MEAN@Wl then X@Wr) accumulate into the same fp32 fragments.
// A and B both load via plain ldmatrix.x4 (B = W[h][k], k-contiguous =
// col-major KxN). smem rows padded to 144B: LDSM conflict-free.
// Dynamic smem 55.3 KB.
// ---------------------------------------------------------------------------
#define RPB 128

__device__ __forceinline__ void split_w(const float* __restrict__ W,
                                        uint16_t* sh, uint16_t* sl, int tid) {
#pragma unroll
    for (int it = 0; it < 4; it++) {
        int i = tid + it * 256;          // 64*16 = 1024
        int h = i >> 4, q = i & 15;
        float4 v = ((const float4*)W)[h * 16 + q];
        store_split(sh, sl, h * BK + q * 4, v);
    }
}

__device__ __forceinline__ void split_a(const float* __restrict__ SRC,
                                        int base, uint16_t* sh, uint16_t* sl,
                                        int tid) {
#pragma unroll
    for (int it = 0; it < 8; it++) {
        int i = tid + it * 256;          // 128*16 = 2048
        int r = i >> 4, q = i & 15;
        int row = base + r;
        float4 v = make_float4(0.f, 0.f, 0.f, 0.f);
        if (row < NN) v = ((const float4*)SRC)[row * 16 + q];
        store_split(sh, sl, r * BK + q * 4, v);
    }
}

__device__ __forceinline__ void mma_phase(uint32_t aH, uint32_t aL,
                                          uint32_t bH, uint32_t bL,
                                          float acc[8][4]) {
#pragma unroll
    for (int kc = 0; kc < 4; kc++) {
        uint32_t ah[4], al[4];
        LDSM4(ah, aH + kc * 32);
        LDSM4(al, aL + kc * 32);
#pragma unroll
        for (int p = 0; p < 4; p++) {
            uint32_t bh[4], blo[4];
            uint32_t boff = p * (16 * BK * 2) + kc * 32;
            LDSM4(bh,  bH + boff);
            LDSM4(blo, bL + boff);
            MMA16816(acc[2 * p],     ah, bh[0],  bh[1]);
            MMA16816(acc[2 * p + 1], ah, bh[2],  bh[3]);
            MMA16816(acc[2 * p],     ah, blo[0], blo[1]);
            MMA16816(acc[2 * p + 1], ah, blo[2], blo[3]);
            MMA16816(acc[2 * p],     al, bh[0],  bh[1]);
            MMA16816(acc[2 * p + 1], al, bh[2],  bh[3]);
        }
    }
}

template <bool RELU>
__global__ void __launch_bounds__(256)
combine_kernel(const float* __restrict__ Xin, const float* __restrict__ MEAN,
               const float* __restrict__ Wl, const float* __restrict__ bl,
               const float* __restrict__ Wr, float* __restrict__ Y) {
    extern __shared__ char smem[];
    uint16_t* sAh = (uint16_t*)smem;                   // [128][BK]
    uint16_t* sAl = (uint16_t*)(smem + 18432);
    uint16_t* sBh = (uint16_t*)(smem + 36864);         // [64][BK]
    uint16_t* sBl = (uint16_t*)(smem + 46080);
    __shared__ float sb[64];

    int tid  = threadIdx.x;
    int lane = tid & 31;
    int w    = tid >> 5;          // 0..7, warp tile: rows [r0, r0+16)
    int base = blockIdx.x * RPB;
    int r0   = w * 16;

    if (tid < 64) sb[tid] = bl[tid];

    // phase-1 tiles: Wl + MEAN
    split_w(Wl, sBh, sBl, tid);
    split_a(MEAN, base, sAh, sAl, tid);
    __syncthreads();

    // fragment addresses (phase-independent)
    uint32_t aAh = smem_u32(sAh) + (uint32_t)((r0 + (lane & 15)) * BK * 2)
                 + (uint32_t)((lane >> 4) * 16);
    uint32_t aAl = aAh + 18432;
    int n_b = ((lane >> 4) << 3) + (lane & 7);
    int kb  = ((lane >> 3) & 1) * 16;
    uint32_t aBh = smem_u32(sBh) + (uint32_t)(n_b * BK * 2) + (uint32_t)kb;
    uint32_t aBl = aBh + 9216;

    // fp32 accumulators initialized with bias (d-fragment layout)
    float acc[8][4];
    int cq = (lane & 3) * 2;
#pragma unroll
    for (int nt = 0; nt < 8; nt++) {
        acc[nt][0] = sb[nt * 8 + cq];
        acc[nt][1] = sb[nt * 8 + cq + 1];
        acc[nt][2] = acc[nt][0];
        acc[nt][3] = acc[nt][1];
    }

    mma_phase(aAh, aAl, aBh, aBl, acc);     // mean @ Wl^T
    __syncthreads();

    // phase-2 tiles: Wr + X (reuse buffers)
    split_w(Wr, sBh, sBl, tid);
    split_a(Xin, base, sAh, sAl, tid);
    __syncthreads();

    mma_phase(aAh, aAl, aBh, aBl, acc);     // + x @ Wr^T

    // epilogue: d-fragment -> Y
    int rA = base + r0 + (lane >> 2);
    int rB = rA + 8;
#pragma unroll
    for (int nt = 0; nt < 8; nt++) {
        int cc = nt * 8 + cq;
        float2 vA = make_float2(acc[nt][0], acc[nt][1]);
        float2 vB = make_float2(acc[nt][2], acc[nt][3]);
        if (RELU) {
            vA.x = fmaxf(vA.x, 0.f); vA.y = fmaxf(vA.y, 0.f);
            vB.x = fmaxf(vB.x, 0.f); vB.y = fmaxf(vB.y, 0.f);
        }
        if (rA < NN) *(float2*)&Y[(size_t)rA * HDIM + cc] = vA;
        if (rB < NN) *(float2*)&Y[(size_t)rB * HDIM + cc] = vB;
    }
}

// ---------------------------------------------------------------------------
// out[e] = dot(Z[u[e]], Z[N_USERS + m[e]]) — 16 lanes per label edge, float4
// ---------------------------------------------------------------------------
__global__ void dot_kernel(const int* __restrict__ eli,
                           const float* __restrict__ Z,
                           float* __restrict__ out) {
    int gw = (blockIdx.x * blockDim.x + threadIdx.x) >> 4;
    int l  = threadIdx.x & 15;
    if (gw >= NEL) return;
    int u = __ldg(&eli[gw]);
    int m = __ldg(&eli[NEL + gw]);
    float4 a = *(const float4*)&Z[(size_t)u * HDIM + l * 4];
    float4 b = *(const float4*)&Z[(size_t)(N_USERS + m) * HDIM + l * 4];
    float s = a.x * b.x + a.y * b.y + a.z * b.z + a.w * b.w;
#pragma unroll
    for (int o = 8; o; o >>= 1) s += __shfl_xor_sync(0xffffffffu, s, o);
    if (l == 0) out[gw] = s;
}

// ---------------------------------------------------------------------------
extern "C" void kernel_launch(void* const* d_in, const int* in_sizes, int n_in,
                              void* d_out, int out_size) {
    const float* movie_x   = (const float*)d_in[0];
    const float* user_emb  = (const float*)d_in[1];
    const float* movie_emb = (const float*)d_in[2];
    const float* lin_W     = (const float*)d_in[3];
    const float* lin_b     = (const float*)d_in[4];
    const float* W1l       = (const float*)d_in[5];
    const float* b1        = (const float*)d_in[6];
    const float* W1r       = (const float*)d_in[7];
    const float* W2l       = (const float*)d_in[8];
    const float* b2        = (const float*)d_in[9];
    const float* W2r       = (const float*)d_in[10];
    const int*   ei        = (const int*)d_in[11];
    const int*   eli       = (const int*)d_in[12];
    float* out = (float*)d_out;

    float *dX, *dY, *dZ, *dM;
    int *dDEGI, *dOFF, *dCUR, *dCSR, *dBSUM;
    cudaGetSymbolAddress((void**)&dX,    g_X);
    cudaGetSymbolAddress((void**)&dY,    g_Y);
    cudaGetSymbolAddress((void**)&dZ,    g_Z);
    cudaGetSymbolAddress((void**)&dM,    g_M);
    cudaGetSymbolAddress((void**)&dDEGI, g_DEGI);
    cudaGetSymbolAddress((void**)&dOFF,  g_OFF);
    cudaGetSymbolAddress((void**)&dCUR,  g_CUR);
    cudaGetSymbolAddress((void**)&dCSR,  g_CSR);
    cudaGetSymbolAddress((void**)&dBSUM, g_BSUM);

    const size_t smemC = 55296;     // 2x(128x72) + 2x(64x72) bf16
    cudaFuncSetAttribute(combine_kernel<true>,
                         cudaFuncAttributeMaxDynamicSharedMemorySize, (int)smemC);
    cudaFuncSetAttribute(combine_kernel<false>,
                         cudaFuncAttributeMaxDynamicSharedMemorySize, (int)smemC);

    const int gridC = (NN + RPB - 1) / RPB;   // 2188
    const int gridG = (NN * 32 + 255) / 256;  // warp per row
    const int gridI = (NN + 3) / 4;           // init+hist (covers NE too)

    // ---- prologue: features + CSR ----
    cudaMemsetAsync(dDEGI, 0, NN * sizeof(int));
    init_hist_kernel<<<gridI, 256>>>(ei, dDEGI, movie_x, user_emb,
                                     movie_emb, lin_W, lin_b, dX);          // #1
    scanA_kernel<<<NB2, 256>>>(dDEGI, dBSUM);                               // #2
    scanB_kernel<<<1, 512>>>(dBSUM, dOFF);                                  // #3
    scanC_kernel<<<NB2, 256>>>(dDEGI, dBSUM, dOFF, dCUR);                   // #4
    fill_kernel<<<(NE + 255) / 256, 256>>>(ei, dCUR, dCSR);                 // #5

    // ---- layer 1 ----
    gather_kernel<<<gridG, 256>>>(dX, dOFF, dCSR, dM);                      // #6
    combine_kernel<true><<<gridC, 256, smemC>>>(dX, dM, W1l, b1, W1r, dY);  // #7

    // ---- layer 2 ----
    gather_kernel<<<gridG, 256>>>(dY, dOFF, dCSR, dM);                      // #8
    combine_kernel<false><<<gridC, 256, smemC>>>(dY, dM, W2l, b2, W2r, dZ); // #9

    // ---- decode ----
    dot_kernel<<<(NEL * 16) / 256, 256>>>(eli, dZ, out);                    // #10
}

// round 13
// speedup vs baseline: 2.4535x; 1.0146x over previous
#include <cuda_runtime.h>
#include <cstddef>
#include <cstdint>

#define N_USERS 200000
#define N_MOVIES 80000
#define NN 280000
#define HDIM 64
#define F_MOVIE 20
#define NE 1250000
#define NEL 500000
#define NB2 274           // ceil(NN / 1024)
#define BK 72             // bf16 row stride (144 bytes) for MMA smem tiles

typedef unsigned long long u64;

// Scratch (static device globals: allowed; runtime allocation is not).
__device__ __align__(16) float g_X[(size_t)NN * HDIM];
__device__ __align__(16) float g_Y[(size_t)NN * HDIM];
__device__ __align__(16) float g_Z[(size_t)NN * HDIM];
__device__ __align__(16) float g_M[(size_t)NN * HDIM];
__device__ int g_DEGI[NN];
__device__ int g_OFF[NN + 1];
__device__ int g_CUR[NN];
__device__ int g_CSR[NE];      // holds src*HDIM (premultiplied)
__device__ int g_BSUM[512];

__device__ __forceinline__ uint32_t smem_u32(const void* p) {
    return (uint32_t)__cvta_generic_to_shared(p);
}

#define LDSM4(d, addr) \
    asm volatile("ldmatrix.sync.aligned.m8n8.x4.shared.b16 {%0,%1,%2,%3}, [%4];" \
                 : "=r"((d)[0]), "=r"((d)[1]), "=r"((d)[2]), "=r"((d)[3]) \
                 : "r"(addr))

#define MMA16816(acc, a, b0v, b1v) \
    asm volatile("mma.sync.aligned.m16n8k16.row.col.f32.bf16.bf16.f32 " \
                 "{%0,%1,%2,%3}, {%4,%5,%6,%7}, {%8,%9}, {%0,%1,%2,%3};" \
                 : "+f"((acc)[0]), "+f"((acc)[1]), "+f"((acc)[2]), "+f"((acc)[3]) \
                 : "r"((a)[0]), "r"((a)[1]), "r"((a)[2]), "r"((a)[3]), \
                   "r"(b0v), "r"(b1v))

// split x -> hi (truncated bf16) + lo (truncated bf16 of exact residual)
__device__ __forceinline__ void store_split(uint16_t* sh, uint16_t* sl,
                                            int off, float4 v) {
    uint32_t ux = __float_as_uint(v.x), uy = __float_as_uint(v.y);
    uint32_t uz = __float_as_uint(v.z), uw = __float_as_uint(v.w);
    float hx = __uint_as_float(ux & 0xFFFF0000u);
    float hy = __uint_as_float(uy & 0xFFFF0000u);
    float hz = __uint_as_float(uz & 0xFFFF0000u);
    float hw = __uint_as_float(uw & 0xFFFF0000u);
    uint32_t h01 = __byte_perm(ux, uy, 0x7632);
    uint32_t h23 = __byte_perm(uz, uw, 0x7632);
    uint32_t l01 = __byte_perm(__float_as_uint(v.x - hx),
                               __float_as_uint(v.y - hy), 0x7632);
    uint32_t l23 = __byte_perm(__float_as_uint(v.z - hz),
                               __float_as_uint(v.w - hw), 0x7632);
    *(uint32_t*)(sh + off)     = h01;
    *(uint32_t*)(sh + off + 2) = h23;
    *(uint32_t*)(sl + off)     = l01;
    *(uint32_t*)(sl + off + 2) = l23;
}

// ---------------------------------------------------------------------------
// 1) fused: X init (row-parallel) + degree histogram (edge-parallel)
// ---------------------------------------------------------------------------
__global__ void init_hist_kernel(const int* __restrict__ ei,
                                 int* __restrict__ degi,
                                 const float* __restrict__ movie_x,
                                 const float* __restrict__ user_emb,
                                 const float* __restrict__ movie_emb,
                                 const float* __restrict__ lin_W,
                                 const float* __restrict__ lin_b,
                                 float* __restrict__ X) {
    int gid = blockIdx.x * blockDim.x + threadIdx.x;
    if (gid < NE) atomicAdd(&degi[ei[NE + gid]], 1);

    __shared__ float sx[4][F_MOVIE];
    int lr  = threadIdx.x >> 6;
    int h   = threadIdx.x & 63;
    int row = blockIdx.x * 4 + lr;
    int mrow = row - N_USERS;
    if (row < NN && mrow >= 0 && h < F_MOVIE)
        sx[lr][h] = movie_x[mrow * F_MOVIE + h];
    __syncthreads();
    if (row >= NN) return;
    if (mrow < 0) {
        X[(size_t)row * HDIM + h] = user_emb[(size_t)row * HDIM + h];
    } else {
        float acc = lin_b[h] + movie_emb[(size_t)mrow * HDIM + h];
#pragma unroll
        for (int f = 0; f < F_MOVIE; f++)
            acc += sx[lr][f] * lin_W[h * F_MOVIE + f];
        X[(size_t)row * HDIM + h] = acc;
    }
}

// ---------------------------------------------------------------------------
// 2) parallel 3-pass exclusive scan (NO serial chain)
// ---------------------------------------------------------------------------
__global__ void scanA_kernel(const int* __restrict__ degi, int* __restrict__ bsum) {
    __shared__ int ws[8];
    int b = blockIdx.x, t = threadIdx.x;
    int i0 = b * 1024 + t * 4;
    int s = 0;
#pragma unroll
    for (int j = 0; j < 4; j++) { int i = i0 + j; s += (i < NN) ? degi[i] : 0; }
#pragma unroll
    for (int o = 16; o; o >>= 1) s += __shfl_xor_sync(0xffffffffu, s, o);
    if ((t & 31) == 0) ws[t >> 5] = s;
    __syncthreads();
    if (t == 0) {
        int tot = 0;
#pragma unroll
        for (int w = 0; w < 8; w++) tot += ws[w];
        bsum[b] = tot;
    }
}

__global__ void scanB_kernel(int* __restrict__ bsum, int* __restrict__ off) {
    __shared__ int s[512];
    int t = threadIdx.x;
    s[t] = (t < NB2) ? bsum[t] : 0;
    __syncthreads();
#pragma unroll
    for (int o = 1; o < 512; o <<= 1) {
        int x = (t >= o) ? s[t - o] : 0;
        __syncthreads();
        s[t] += x;
        __syncthreads();
    }
    int excl = (t == 0) ? 0 : s[t - 1];
    if (t < NB2) bsum[t] = excl;
    if (t == 0) off[NN] = NE;
}

__global__ void scanC_kernel(const int* __restrict__ degi,
                             const int* __restrict__ boff,
                             int* __restrict__ off, int* __restrict__ cur) {
    __shared__ int ss[256];
    int b = blockIdx.x, t = threadIdx.x;
    int i0 = b * 1024 + t * 4;
    int v[4];
    int tot = 0;
#pragma unroll
    for (int j = 0; j < 4; j++) {
        int i = i0 + j;
        v[j] = (i < NN) ? degi[i] : 0;
        tot += v[j];
    }
    ss[t] = tot;
    __syncthreads();
#pragma unroll
    for (int o = 1; o < 256; o <<= 1) {
        int x = (t >= o) ? ss[t - o] : 0;
        __syncthreads();
        ss[t] += x;
        __syncthreads();
    }
    int run = boff[b] + ((t == 0) ? 0 : ss[t - 1]);
#pragma unroll
    for (int j = 0; j < 4; j++) {
        int i = i0 + j;
        if (i < NN) { off[i] = run; cur[i] = run; }
        run += v[j];
    }
}

// ---------------------------------------------------------------------------
// 3) CSR fill — stores src*HDIM so gather needs no multiply
// ---------------------------------------------------------------------------
__global__ void fill_kernel(const int* __restrict__ ei,
                            int* __restrict__ cur, int* __restrict__ csr) {
    int e = blockIdx.x * blockDim.x + threadIdx.x;
    if (e >= NE) return;
    int src = ei[e];
    int dst = ei[NE + e];
    int p = atomicAdd(&cur[dst], 1);
    csr[p] = src * HDIM;
}

// ---------------------------------------------------------------------------
// 4) MEAN[row] = mean over neighbors — warp per row, float2 lanes, MLP=8
// ---------------------------------------------------------------------------
__global__ void __launch_bounds__(256)
gather_kernel(const float* __restrict__ Xin,
              const int* __restrict__ off, const int* __restrict__ csr,
              float* __restrict__ MEAN) {
    int row  = (blockIdx.x * blockDim.x + threadIdx.x) >> 5;
    int lane = threadIdx.x & 31;
    if (row >= NN) return;
    int s0 = __ldg(&off[row]);
    int s1 = __ldg(&off[row + 1]);
    const float* Xl = Xin + lane * 2;
    float2 acc = make_float2(0.f, 0.f);
    for (int e = s0; e < s1; e += 8) {
        int idx[8];
        float2 v[8];
#pragma unroll
        for (int j = 0; j < 8; j++)
            idx[j] = (e + j < s1) ? __ldg(&csr[e + j]) : -1;
#pragma unroll
        for (int j = 0; j < 8; j++)
            v[j] = (idx[j] >= 0) ? *(const float2*)(Xl + idx[j])
                                 : make_float2(0.f, 0.f);
#pragma unroll
        for (int j = 0; j < 8; j++) { acc.x += v[j].x; acc.y += v[j].y; }
    }
    float inv = 1.f / fmaxf((float)(s1 - s0), 1.f);
    acc.x *= inv; acc.y *= inv;
    *(float2*)&MEAN[(size_t)row * HDIM + lane * 2] = acc;
}

// ---------------------------------------------------------------------------
// Y = act( MEAN @ Wl.T + bl + Xin @ Wr.T )  — tensor-core combine, PRELOADED.
// All four tiles (MEAN, X, Wl, Wr) split to bf16 hi/lo up front; ONE
// __syncthreads; then an uninterrupted 2x96-MMA stream per warp.
// smem 110.6 KB -> 2 blocks/SM (16 warps).
// ---------------------------------------------------------------------------
#define RPB 128
#define A_BYTES 18432      // 128 x BK x 2
#define B_BYTES 9216       // 64 x BK x 2

__device__ __forceinline__ void split_w(const float* __restrict__ W,
                                        uint16_t* sh, uint16_t* sl, int tid) {
#pragma unroll
    for (int it = 0; it < 4; it++) {
        int i = tid + it * 256;          // 64*16 = 1024
        int h = i >> 4, q = i & 15;
        float4 v = ((const float4*)W)[h * 16 + q];
        store_split(sh, sl, h * BK + q * 4, v);
    }
}

__device__ __forceinline__ void split_a(const float* __restrict__ SRC,
                                        int base, uint16_t* sh, uint16_t* sl,
                                        int tid) {
#pragma unroll
    for (int it = 0; it < 8; it++) {
        int i = tid + it * 256;          // 128*16 = 2048
        int r = i >> 4, q = i & 15;
        int row = base + r;
        float4 v = make_float4(0.f, 0.f, 0.f, 0.f);
        if (row < NN) v = ((const float4*)SRC)[row * 16 + q];
        store_split(sh, sl, r * BK + q * 4, v);
    }
}

__device__ __forceinline__ void mma_phase(uint32_t aH, uint32_t aL,
                                          uint32_t bH, uint32_t bL,
                                          float acc[8][4]) {
#pragma unroll
    for (int kc = 0; kc < 4; kc++) {
        uint32_t ah[4], al[4];
        LDSM4(ah, aH + kc * 32);
        LDSM4(al, aL + kc * 32);
#pragma unroll
        for (int p = 0; p < 4; p++) {
            uint32_t bh[4], blo[4];
            uint32_t boff = p * (16 * BK * 2) + kc * 32;
            LDSM4(bh,  bH + boff);
            LDSM4(blo, bL + boff);
            MMA16816(acc[2 * p],     ah, bh[0],  bh[1]);
            MMA16816(acc[2 * p + 1], ah, bh[2],  bh[3]);
            MMA16816(acc[2 * p],     ah, blo[0], blo[1]);
            MMA16816(acc[2 * p + 1], ah, blo[2], blo[3]);
            MMA16816(acc[2 * p],     al, bh[0],  bh[1]);
            MMA16816(acc[2 * p + 1], al, bh[2],  bh[3]);
        }
    }
}

template <bool RELU>
__global__ void __launch_bounds__(256)
combine_kernel(const float* __restrict__ Xin, const float* __restrict__ MEAN,
               const float* __restrict__ Wl, const float* __restrict__ bl,
               const float* __restrict__ Wr, float* __restrict__ Y) {
    extern __shared__ char smem[];
    // layout: [Mh][Ml][Xh][Xl][Wlh][Wll][Wrh][Wrl]
    uint16_t* sMh  = (uint16_t*)smem;
    uint16_t* sMl  = (uint16_t*)(smem + A_BYTES);
    uint16_t* sXh  = (uint16_t*)(smem + 2 * A_BYTES);
    uint16_t* sXl  = (uint16_t*)(smem + 3 * A_BYTES);
    uint16_t* sWlh = (uint16_t*)(smem + 4 * A_BYTES);
    uint16_t* sWll = (uint16_t*)(smem + 4 * A_BYTES + B_BYTES);
    uint16_t* sWrh = (uint16_t*)(smem + 4 * A_BYTES + 2 * B_BYTES);
    uint16_t* sWrl = (uint16_t*)(smem + 4 * A_BYTES + 3 * B_BYTES);
    __shared__ float sb[64];

    int tid  = threadIdx.x;
    int lane = tid & 31;
    int w    = tid >> 5;          // 0..7, warp tile: rows [r0, r0+16)
    int base = blockIdx.x * RPB;
    int r0   = w * 16;

    if (tid < 64) sb[tid] = bl[tid];

    // preload ALL tiles, one sync
    split_w(Wl, sWlh, sWll, tid);
    split_w(Wr, sWrh, sWrl, tid);
    split_a(MEAN, base, sMh, sMl, tid);
    split_a(Xin,  base, sXh, sXl, tid);
    __syncthreads();

    // fragment addresses
    uint32_t aoff = (uint32_t)((r0 + (lane & 15)) * BK * 2)
                  + (uint32_t)((lane >> 4) * 16);
    uint32_t aMh = smem_u32(sMh) + aoff;
    uint32_t aMl = aMh + A_BYTES;
    uint32_t aXh = smem_u32(sXh) + aoff;
    uint32_t aXl = aXh + A_BYTES;
    int n_b = ((lane >> 4) << 3) + (lane & 7);
    int kb  = ((lane >> 3) & 1) * 16;
    uint32_t boff = (uint32_t)(n_b * BK * 2) + (uint32_t)kb;
    uint32_t aBlh = smem_u32(sWlh) + boff;
    uint32_t aBll = aBlh + B_BYTES;
    uint32_t aBrh = smem_u32(sWrh) + boff;
    uint32_t aBrl = aBrh + B_BYTES;

    // fp32 accumulators initialized with bias (d-fragment layout)
    float acc[8][4];
    int cq = (lane & 3) * 2;
#pragma unroll
    for (int nt = 0; nt < 8; nt++) {
        acc[nt][0] = sb[nt * 8 + cq];
        acc[nt][1] = sb[nt * 8 + cq + 1];
        acc[nt][2] = acc[nt][0];
        acc[nt][3] = acc[nt][1];
    }

    mma_phase(aMh, aMl, aBlh, aBll, acc);   // mean @ Wl^T
    mma_phase(aXh, aXl, aBrh, aBrl, acc);   // + x @ Wr^T

    // epilogue: d-fragment -> Y
    int rA = base + r0 + (lane >> 2);
    int rB = rA + 8;
#pragma unroll
    for (int nt = 0; nt < 8; nt++) {
        int cc = nt * 8 + cq;
        float2 vA = make_float2(acc[nt][0], acc[nt][1]);
        float2 vB = make_float2(acc[nt][2], acc[nt][3]);
        if (RELU) {
            vA.x = fmaxf(vA.x, 0.f); vA.y = fmaxf(vA.y, 0.f);
            vB.x = fmaxf(vB.x, 0.f); vB.y = fmaxf(vB.y, 0.f);
        }
        if (rA < NN) *(float2*)&Y[(size_t)rA * HDIM + cc] = vA;
        if (rB < NN) *(float2*)&Y[(size_t)rB * HDIM + cc] = vB;
    }
}

// ---------------------------------------------------------------------------
// out[e] = dot(Z[u[e]], Z[N_USERS + m[e]]) — 16 lanes per label edge, float4
// ---------------------------------------------------------------------------
__global__ void dot_kernel(const int* __restrict__ eli,
                           const float* __restrict__ Z,
                           float* __restrict__ out) {
    int gw = (blockIdx.x * blockDim.x + threadIdx.x) >> 4;
    int l  = threadIdx.x & 15;
    if (gw >= NEL) return;
    int u = __ldg(&eli[gw]);
    int m = __ldg(&eli[NEL + gw]);
    float4 a = *(const float4*)&Z[(size_t)u * HDIM + l * 4];
    float4 b = *(const float4*)&Z[(size_t)(N_USERS + m) * HDIM + l * 4];
    float s = a.x * b.x + a.y * b.y + a.z * b.z + a.w * b.w;
#pragma unroll
    for (int o = 8; o; o >>= 1) s += __shfl_xor_sync(0xffffffffu, s, o);
    if (l == 0) out[gw] = s;
}

// ---------------------------------------------------------------------------
extern "C" void kernel_launch(void* const* d_in, const int* in_sizes, int n_in,
                              void* d_out, int out_size) {
    const float* movie_x   = (const float*)d_in[0];
    const float* user_emb  = (const float*)d_in[1];
    const float* movie_emb = (const float*)d_in[2];
    const float* lin_W     = (const float*)d_in[3];
    const float* lin_b     = (const float*)d_in[4];
    const float* W1l       = (const float*)d_in[5];
    const float* b1        = (const float*)d_in[6];
    const float* W1r       = (const float*)d_in[7];
    const float* W2l       = (const float*)d_in[8];
    const float* b2        = (const float*)d_in[9];
    const float* W2r       = (const float*)d_in[10];
    const int*   ei        = (const int*)d_in[11];
    const int*   eli       = (const int*)d_in[12];
    float* out = (float*)d_out;

    float *dX, *dY, *dZ, *dM;
    int *dDEGI, *dOFF, *dCUR, *dCSR, *dBSUM;
    cudaGetSymbolAddress((void**)&dX,    g_X);
    cudaGetSymbolAddress((void**)&dY,    g_Y);
    cudaGetSymbolAddress((void**)&dZ,    g_Z);
    cudaGetSymbolAddress((void**)&dM,    g_M);
    cudaGetSymbolAddress((void**)&dDEGI, g_DEGI);
    cudaGetSymbolAddress((void**)&dOFF,  g_OFF);
    cudaGetSymbolAddress((void**)&dCUR,  g_CUR);
    cudaGetSymbolAddress((void**)&dCSR,  g_CSR);
    cudaGetSymbolAddress((void**)&dBSUM, g_BSUM);

    const size_t smemC = 4 * A_BYTES + 4 * B_BYTES;   // 110,592 B
    cudaFuncSetAttribute(combine_kernel<true>,
                         cudaFuncAttributeMaxDynamicSharedMemorySize, (int)smemC);
    cudaFuncSetAttribute(combine_kernel<false>,
                         cudaFuncAttributeMaxDynamicSharedMemorySize, (int)smemC);

    const int gridC = (NN + RPB - 1) / RPB;   // 2188
    const int gridG = (NN * 32 + 255) / 256;  // warp per row
    const int gridI = (NN + 3) / 4;           // init+hist (covers NE too)

    // ---- prologue: features + CSR ----
    cudaMemsetAsync(dDEGI, 0, NN * sizeof(int));
    init_hist_kernel<<<gridI, 256>>>(ei, dDEGI, movie_x, user_emb,
                                     movie_emb, lin_W, lin_b, dX);          // #1
    scanA_kernel<<<NB2, 256>>>(dDEGI, dBSUM);                               // #2
    scanB_kernel<<<1, 512>>>(dBSUM, dOFF);                                  // #3
    scanC_kernel<<<NB2, 256>>>(dDEGI, dBSUM, dOFF, dCUR);                   // #4
    fill_kernel<<<(NE + 255) / 256, 256>>>(ei, dCUR, dCSR);                 // #5

    // ---- layer 1 ----
    gather_kernel<<<gridG, 256>>>(dX, dOFF, dCSR, dM);                      // #6
    combine_kernel<true><<<gridC, 256, smemC>>>(dX, dM, W1l, b1, W1r, dY);  // #7

    // ---- layer 2 ----
    gather_kernel<<<gridG, 256>>>(dY, dOFF, dCSR, dM);                      // #8
    combine_kernel<false><<<gridC, 256, smemC>>>(dY, dM, W2l, b2, W2r, dZ); // #9

    // ---- decode ----
    dot_kernel<<<(NEL * 16) / 256, 256>>>(eli, dZ, out);                    // #10
}